// round 4
// baseline (speedup 1.0000x reference)
#include <cuda_runtime.h>
#include <cstdint>

#define NCTA 128
#define NTHR 256
#define TQ   200
#define INF  171
#define OUTF 171
#define HIDQ 1024
#define KSX  22            // x-part k-steps (176 padded cols)
#define KSH  128           // h-part k-steps (1024 cols)
#define KS1  (KSX + KSH)   // 150
#define KS2  (2 * KSH)     // 256
#define KSD  KSH
#define DCTA 22
#define HFR  (KSH * 1024)  // floats per parity of an h activation buffer
#define XFR  (KSX * 1024)  // floats per x/out fragment block

// ------------------- persistent device state (static, no allocs) -------------------
__device__ __align__(16) float2 g_W1[NCTA * KS1 * 4 * 32];   // 19.7 MB
__device__ __align__(16) float2 g_W2[NCTA * KS2 * 4 * 32];   // 33.6 MB
__device__ __align__(16) float2 g_W3[NCTA * KS2 * 4 * 32];   // 33.6 MB
__device__ __align__(16) float2 g_Wd[DCTA * KSD * 32];       // 0.7 MB
__device__ float g_bias1[4 * HIDQ];
__device__ float g_bias2[4 * HIDQ];
__device__ float g_bias3[4 * HIDQ];
__device__ float g_biasd[176];
__device__ __align__(16) float g_xfrag[TQ * XFR];            // 18 MB: real_seq pre-formatted
__device__ __align__(16) float g_h1[2 * HFR];
__device__ __align__(16) float g_h2[2 * HFR];
__device__ __align__(16) float g_h3[2 * HFR];
__device__ __align__(16) float g_of[2 * XFR];                // decoder out fragments
__device__ unsigned g_cnt;
__device__ volatile unsigned g_gen;

// ----------------------------- small helpers -----------------------------
__device__ __forceinline__ float tf32r(float x) {
    uint32_t y;
    asm("cvt.rna.tf32.f32 %0, %1;" : "=r"(y) : "f"(x));
    return __uint_as_float(y);
}

__device__ __forceinline__ void mma8(float* c, uint32_t a0, uint32_t a1, uint32_t a2,
                                     uint32_t a3, uint32_t b0, uint32_t b1) {
    asm("mma.sync.aligned.m16n8k8.row.col.f32.tf32.tf32.f32 "
        "{%0,%1,%2,%3},{%4,%5,%6,%7},{%8,%9},{%0,%1,%2,%3};"
        : "+f"(c[0]), "+f"(c[1]), "+f"(c[2]), "+f"(c[3])
        : "r"(a0), "r"(a1), "r"(a2), "r"(a3), "r"(b0), "r"(b1));
}

__device__ __forceinline__ float sigm(float x) { return 1.f / (1.f + __expf(-x)); }

// grid-wide spin barrier (all 128 CTAs resident: 1 CTA/SM, grid 128 <= 148 SMs)
__device__ __forceinline__ void gridbar(unsigned gen) {
    __syncthreads();
    if (threadIdx.x == 0) {
        __threadfence();
        unsigned arr = atomicAdd(&g_cnt, 1u);
        if (arr == NCTA - 1u) {
            g_cnt = 0u;
            __threadfence();
            g_gen = gen;
        } else {
            while (g_gen != gen) { __nanosleep(32); }
        }
        __threadfence();
    }
    __syncthreads();
}

__device__ __forceinline__ void initacc(float acc[16], const float* bias, int ct, int lane) {
#pragma unroll
    for (int nt = 0; nt < 4; ++nt) {
        int col = nt * HIDQ + (ct << 3) + ((lane & 3) << 1);
        float b0 = bias[col], b1 = bias[col + 1];
        acc[4 * nt] = b0; acc[4 * nt + 1] = b1;
        acc[4 * nt + 2] = b0; acc[4 * nt + 3] = b1;
    }
}

// accumulate nks k-steps; A in fragment layout [ks][mt][lane]{a0..a3}; wp pre-offset by lane
__device__ __forceinline__ const float2* mma_span(float acc[16], const float* A, int nks,
                                                  int w, int lane, const float2* wp) {
    const float4* A4 = (const float4*)A;
#pragma unroll 2
    for (int ks = 0; ks < nks; ++ks) {
        float4 a = __ldcg(A4 + (ks * 8 + w) * 32 + lane);
        uint32_t a0 = __float_as_uint(a.x), a1 = __float_as_uint(a.y);
        uint32_t a2 = __float_as_uint(a.z), a3 = __float_as_uint(a.w);
#pragma unroll
        for (int nt = 0; nt < 4; ++nt) {
            float2 b = wp[nt * 32];
            mma8(acc + 4 * nt, a0, a1, a2, a3, __float_as_uint(b.x), __float_as_uint(b.y));
        }
        wp += 128;
    }
    return wp;
}

// LSTM cell epilogue: gates -> c,h; scatter h into fragment layout for next consumers
__device__ __forceinline__ void lstm_epi(const float acc[16], float cst[4], float* hdst,
                                         int ct, int w, int lane) {
#pragma unroll
    for (int j = 0; j < 4; ++j) {
        float ig = sigm(acc[0 + j]);
        float fg = sigm(acc[4 + j]);
        float gg = tanhf(acc[8 + j]);
        float og = sigm(acc[12 + j]);
        float cc = fg * cst[j] + ig * gg;
        cst[j] = cc;
        float h = og * tanhf(cc);
        int r = (lane >> 2) + ((j & 2) << 2);       // 0..15
        int c = ((lane & 3) << 1) + (j & 1);        // 0..7
        int aq = ((c >= 4) ? 2 : 0) + ((r >= 8) ? 1 : 0);
        int lp = ((r & 7) << 2) + (c & 3);
        hdst[((((ct << 3) + w) << 5) + lp) * 4 + aq] = tf32r(h);
    }
}

// ----------------------------- setup kernels -----------------------------
__device__ __forceinline__ float wfetch(const float* Wih, const float* Whh, int gr, int k,
                                        int kxt, int kxv) {
    if (k < kxt) return (k < kxv) ? Wih[gr * kxv + k] : 0.f;
    return Whh[gr * HIDQ + (k - kxt)];
}

__global__ void fmt_layer(int which, const float* __restrict__ Wih,
                          const float* __restrict__ Whh, int KS, int kxt, int kxv) {
    int idx = blockIdx.x * blockDim.x + threadIdx.x;
    if (idx >= NCTA * KS * 128) return;
    float2* dst = (which == 0) ? g_W1 : (which == 1) ? g_W2 : g_W3;
    int lane = idx & 31;
    int nt = (idx >> 5) & 3;
    int ks = (idx >> 7) % KS;
    int ct = idx / (KS * 128);
    int gr = nt * HIDQ + (ct << 3) + (lane >> 2);
    int k0 = (ks << 3) + (lane & 3);
    float v0 = wfetch(Wih, Whh, gr, k0, kxt, kxv);
    float v1 = wfetch(Wih, Whh, gr, k0 + 4, kxt, kxv);
    dst[idx] = make_float2(tf32r(v0), tf32r(v1));
}

__global__ void fmt_dec(const float* __restrict__ Wdec) {
    int idx = blockIdx.x * blockDim.x + threadIdx.x;
    if (idx >= DCTA * KSD * 32) return;
    int lane = idx & 31;
    int ks = (idx >> 5) % KSD;
    int ct = idx / (KSD * 32);
    int orow = (ct << 3) + (lane >> 2);
    int k0 = (ks << 3) + (lane & 3);
    float v0 = (orow < OUTF) ? Wdec[orow * HIDQ + k0] : 0.f;
    float v1 = (orow < OUTF) ? Wdec[orow * HIDQ + k0 + 4] : 0.f;
    g_Wd[idx] = make_float2(tf32r(v0), tf32r(v1));
}

__global__ void fmt_bias(const float* bi1, const float* bh1, const float* bi2,
                         const float* bh2, const float* bi3, const float* bh3,
                         const float* bd) {
    int i = blockIdx.x * blockDim.x + threadIdx.x;
    if (i < 4096) g_bias1[i] = bi1[i] + bh1[i];
    else if (i < 8192) { int k = i - 4096; g_bias2[k] = bi2[k] + bh2[k]; }
    else if (i < 12288) { int k = i - 8192; g_bias3[k] = bi3[k] + bh3[k]; }
    else if (i < 12288 + 176) { int oc = i - 12288; g_biasd[oc] = (oc < OUTF) ? bd[oc] : 0.f; }
}

__device__ __forceinline__ float ldx(const float* s, int b, int t, int f) {
    return (f < INF) ? tf32r(s[(b * TQ + t) * INF + f]) : 0.f;
}

__global__ void fmt_x(const float* __restrict__ seq) {
    int idx = blockIdx.x * blockDim.x + threadIdx.x;
    if (idx >= TQ * KSX * 8 * 32) return;
    int lane = idx & 31;
    int mt = (idx >> 5) & 7;
    int ks = (idx >> 8) % KSX;
    int t = idx / (KSX * 256);
    int r = lane >> 2, cc = lane & 3;
    int b0 = (mt << 4) + r;
    int f0 = (ks << 3) + cc;
    float4 v = make_float4(ldx(seq, b0, t, f0), ldx(seq, b0 + 8, t, f0),
                           ldx(seq, b0, t, f0 + 4), ldx(seq, b0 + 8, t, f0 + 4));
    ((float4*)g_xfrag)[idx] = v;
}

__global__ void setup_zero() {
    int i = blockIdx.x * blockDim.x + threadIdx.x;
    if (i == 0) { g_cnt = 0u; g_gen = 0u; }
    if (i < 2 * HFR) { g_h1[i] = 0.f; g_h2[i] = 0.f; g_h3[i] = 0.f; }
    if (i < 2 * XFR) { g_of[i] = 0.f; }
}

// ----------------------------- persistent main kernel -----------------------------
__global__ void __launch_bounds__(NTHR, 1)
lstm_main(const int* __restrict__ pcn, const int* __restrict__ pgn, float* __restrict__ out) {
    int ct = blockIdx.x, tid = threadIdx.x, w = tid >> 5, lane = tid & 31;
    int cn = *pcn, gn = *pgn;
    int cyc = cn + gn;
    if (cyc <= 0) cyc = 1;
    float c1[4] = {0, 0, 0, 0}, c2[4] = {0, 0, 0, 0}, c3[4] = {0, 0, 0, 0};
    unsigned gen = 0;
    float acc[16];

    for (int t = 0; t < TQ; ++t) {
        int p = t & 1, q = p ^ 1;
        int use_gt = (t % cyc) < gn;
        const float* xsrc = use_gt ? (g_xfrag + (size_t)t * XFR) : (g_of + (size_t)q * XFR);

        // ---- layer 1: A = [x(176) | h0_prev(1024)] ----
        {
            const float2* wp = g_W1 + (size_t)ct * KS1 * 128 + lane;
            initacc(acc, g_bias1, ct, lane);
            wp = mma_span(acc, xsrc, KSX, w, lane, wp);
            wp = mma_span(acc, g_h1 + (size_t)q * HFR, KSH, w, lane, wp);
            lstm_epi(acc, c1, g_h1 + (size_t)p * HFR, ct, w, lane);
        }
        gen++; gridbar(gen);

        // ---- layer 2: A = [h0_cur | h1_prev] ----
        {
            const float2* wp = g_W2 + (size_t)ct * KS2 * 128 + lane;
            initacc(acc, g_bias2, ct, lane);
            wp = mma_span(acc, g_h1 + (size_t)p * HFR, KSH, w, lane, wp);
            wp = mma_span(acc, g_h2 + (size_t)q * HFR, KSH, w, lane, wp);
            lstm_epi(acc, c2, g_h2 + (size_t)p * HFR, ct, w, lane);
        }
        gen++; gridbar(gen);

        // ---- layer 3: A = [h1_cur | h2_prev] ----
        {
            const float2* wp = g_W3 + (size_t)ct * KS2 * 128 + lane;
            initacc(acc, g_bias3, ct, lane);
            wp = mma_span(acc, g_h2 + (size_t)p * HFR, KSH, w, lane, wp);
            wp = mma_span(acc, g_h3 + (size_t)q * HFR, KSH, w, lane, wp);
            lstm_epi(acc, c3, g_h3 + (size_t)p * HFR, ct, w, lane);
        }
        gen++; gridbar(gen);

        // ---- decoder (CTAs 0..21): out = h3 @ Wdec^T + b ----
        if (ct < DCTA) {
            float d0 = g_biasd[(ct << 3) + ((lane & 3) << 1)];
            float d1 = g_biasd[(ct << 3) + ((lane & 3) << 1) + 1];
            float dacc[4] = {d0, d1, d0, d1};
            const float2* wp = g_Wd + (size_t)ct * KSD * 32 + lane;
            const float4* A4 = (const float4*)(g_h3 + (size_t)p * HFR);
#pragma unroll 2
            for (int ks = 0; ks < KSD; ++ks) {
                float4 a = __ldcg(A4 + (ks * 8 + w) * 32 + lane);
                float2 b = wp[0];
                mma8(dacc, __float_as_uint(a.x), __float_as_uint(a.y), __float_as_uint(a.z),
                     __float_as_uint(a.w), __float_as_uint(b.x), __float_as_uint(b.y));
                wp += 32;
            }
            float* ofr = g_of + (size_t)p * XFR;
#pragma unroll
            for (int j = 0; j < 4; ++j) {
                int r = (lane >> 2) + ((j & 2) << 2);
                int c = ((lane & 3) << 1) + (j & 1);
                int b = (w << 4) + r;
                int oc = (ct << 3) + c;
                if (oc < OUTF) out[(b * TQ + t) * OUTF + oc] = dacc[j];
                int aq = ((c >= 4) ? 2 : 0) + ((r >= 8) ? 1 : 0);
                int lp = ((r & 7) << 2) + (c & 3);
                ofr[((((ct << 3) + w) << 5) + lp) * 4 + aq] = tf32r(dacc[j]);
            }
        }
        gen++; gridbar(gen);
    }
}

// ----------------------------- launcher -----------------------------
extern "C" void kernel_launch(void* const* d_in, const int* in_sizes, int n_in,
                              void* d_out, int out_size) {
    const float* seq  = (const float*)d_in[0];
    const int*   pcn  = (const int*)d_in[1];
    const int*   pgn  = (const int*)d_in[2];
    const float* Wih1 = (const float*)d_in[3];
    const float* Whh1 = (const float*)d_in[4];
    const float* bih1 = (const float*)d_in[5];
    const float* bhh1 = (const float*)d_in[6];
    const float* Wih2 = (const float*)d_in[7];
    const float* Whh2 = (const float*)d_in[8];
    const float* bih2 = (const float*)d_in[9];
    const float* bhh2 = (const float*)d_in[10];
    const float* Wih3 = (const float*)d_in[11];
    const float* Whh3 = (const float*)d_in[12];
    const float* bih3 = (const float*)d_in[13];
    const float* bhh3 = (const float*)d_in[14];
    const float* Wdec = (const float*)d_in[15];
    const float* bdec = (const float*)d_in[16];

    setup_zero<<<(2 * HFR + 255) / 256, 256>>>();
    fmt_bias<<<(12288 + 176 + 255) / 256, 256>>>(bih1, bhh1, bih2, bhh2, bih3, bhh3, bdec);
    fmt_layer<<<(NCTA * KS1 * 128 + 255) / 256, 256>>>(0, Wih1, Whh1, KS1, 176, 171);
    fmt_layer<<<(NCTA * KS2 * 128 + 255) / 256, 256>>>(1, Wih2, Whh2, KS2, 1024, 1024);
    fmt_layer<<<(NCTA * KS2 * 128 + 255) / 256, 256>>>(2, Wih3, Whh3, KS2, 1024, 1024);
    fmt_dec<<<(DCTA * KSD * 32 + 255) / 256, 256>>>(Wdec);
    fmt_x<<<(TQ * KSX * 256 + 255) / 256, 256>>>(seq);
    lstm_main<<<NCTA, NTHR>>>(pcn, pgn, (float*)d_out);
}

// round 5
// speedup vs baseline: 2.1338x; 2.1338x over previous
#include <cuda_runtime.h>
#include <cstdint>

#define NCTA 128
#define NTHR 256
#define TQ   200
#define INF  171
#define OUTF 171
#define HIDQ 1024
#define KSX  32            // x-part k-steps (256 padded cols)
#define KSH  128           // h-part k-steps (1024 cols)
#define KS1  (KSX + KSH)   // 160
#define KS2  (2 * KSH)     // 256
#define KSD  KSH
#define DCTA 22
#define HFR  (KSH * 1024)  // floats per parity of an h activation buffer
#define XFR  (KSX * 1024)  // floats per x/out fragment block

// ------------------- persistent device state (static, no allocs) -------------------
__device__ __align__(16) float2 g_W1[NCTA * KS1 * 128];      // 21 MB, lane-contig nt layout
__device__ __align__(16) float2 g_W2[NCTA * KS2 * 128];      // 33.6 MB
__device__ __align__(16) float2 g_W3[NCTA * KS2 * 128];      // 33.6 MB
__device__ __align__(16) float2 g_Wd[DCTA * KSD * 32];       // 0.7 MB
__device__ float g_bias1[4 * HIDQ];
__device__ float g_bias2[4 * HIDQ];
__device__ float g_bias3[4 * HIDQ];
__device__ float g_biasd[176];
__device__ __align__(16) float g_xfrag[TQ * XFR];            // 26 MB: real_seq pre-formatted
__device__ __align__(16) float g_h1[2 * HFR];
__device__ __align__(16) float g_h2[2 * HFR];
__device__ __align__(16) float g_h3[2 * HFR];
__device__ __align__(16) float g_of[2 * XFR];                // decoder out fragments
__device__ unsigned g_cnt;
__device__ volatile unsigned g_gen;

// ----------------------------- small helpers -----------------------------
__device__ __forceinline__ float tf32r(float x) {
    uint32_t y;
    asm("cvt.rna.tf32.f32 %0, %1;" : "=r"(y) : "f"(x));
    return __uint_as_float(y);
}

__device__ __forceinline__ void mma8(float* c, uint32_t a0, uint32_t a1, uint32_t a2,
                                     uint32_t a3, uint32_t b0, uint32_t b1) {
    asm("mma.sync.aligned.m16n8k8.row.col.f32.tf32.tf32.f32 "
        "{%0,%1,%2,%3},{%4,%5,%6,%7},{%8,%9},{%0,%1,%2,%3};"
        : "+f"(c[0]), "+f"(c[1]), "+f"(c[2]), "+f"(c[3])
        : "r"(a0), "r"(a1), "r"(a2), "r"(a3), "r"(b0), "r"(b1));
}

__device__ __forceinline__ float sigm(float x) { return 1.f / (1.f + __expf(-x)); }

// grid-wide spin barrier (all 128 CTAs resident: 1 CTA/SM, grid 128 <= 148 SMs)
__device__ __forceinline__ void gridbar(unsigned gen) {
    __syncthreads();
    if (threadIdx.x == 0) {
        __threadfence();
        unsigned arr = atomicAdd(&g_cnt, 1u);
        if (arr == NCTA - 1u) {
            g_cnt = 0u;
            __threadfence();
            g_gen = gen;
        } else {
            while (g_gen != gen) { __nanosleep(32); }
        }
        __threadfence();
    }
    __syncthreads();
}

__device__ __forceinline__ void initacc(float acc[16], const float* bias, int ct, int lane) {
#pragma unroll
    for (int nt = 0; nt < 4; ++nt) {
        int col = nt * HIDQ + (ct << 3) + ((lane & 3) << 1);
        float b0 = bias[col], b1 = bias[col + 1];
        acc[4 * nt] = b0; acc[4 * nt + 1] = b1;
        acc[4 * nt + 2] = b0; acc[4 * nt + 3] = b1;
    }
}

// pipelined span: depth-8 register ring for A (L2, __ldcg) and W (L1, default).
// A fragment layout [ks][mt=8][lane]{float4}. W layout per ks: 32 lanes * 2 float4.
// wq pre-offset to span start. nks must be a multiple of 8.
__device__ __forceinline__ void mma_span(float acc[16], const float* A, int nks,
                                         int w, int lane, const float4* wq) {
    const float4* A4 = (const float4*)A;
    float4 ab[8], w0b[8], w1b[8];
    int wl = lane << 1;
#pragma unroll
    for (int i = 0; i < 8; ++i) {
        ab[i]  = __ldcg(A4 + (i * 8 + w) * 32 + lane);
        w0b[i] = wq[i * 64 + wl];
        w1b[i] = wq[i * 64 + wl + 1];
    }
#pragma unroll 8
    for (int ks = 0; ks < nks; ++ks) {
        int s = ks & 7;
        float4 a = ab[s], w0 = w0b[s], w1 = w1b[s];
        int pf = ks + 8;
        if (pf < nks) {
            ab[s]  = __ldcg(A4 + (pf * 8 + w) * 32 + lane);
            w0b[s] = wq[pf * 64 + wl];
            w1b[s] = wq[pf * 64 + wl + 1];
        }
        uint32_t a0 = __float_as_uint(a.x), a1 = __float_as_uint(a.y);
        uint32_t a2 = __float_as_uint(a.z), a3 = __float_as_uint(a.w);
        mma8(acc + 0,  a0, a1, a2, a3, __float_as_uint(w0.x), __float_as_uint(w0.y));
        mma8(acc + 4,  a0, a1, a2, a3, __float_as_uint(w0.z), __float_as_uint(w0.w));
        mma8(acc + 8,  a0, a1, a2, a3, __float_as_uint(w1.x), __float_as_uint(w1.y));
        mma8(acc + 12, a0, a1, a2, a3, __float_as_uint(w1.z), __float_as_uint(w1.w));
    }
}

// LSTM cell epilogue: gates -> c,h; scatter h into fragment layout for next consumers
__device__ __forceinline__ void lstm_epi(const float acc[16], float cst[4], float* hdst,
                                         int ct, int w, int lane) {
#pragma unroll
    for (int j = 0; j < 4; ++j) {
        float ig = sigm(acc[0 + j]);
        float fg = sigm(acc[4 + j]);
        float gg = tanhf(acc[8 + j]);
        float og = sigm(acc[12 + j]);
        float cc = fg * cst[j] + ig * gg;
        cst[j] = cc;
        float h = og * tanhf(cc);
        int r = (lane >> 2) + ((j & 2) << 2);       // 0..15
        int c = ((lane & 3) << 1) + (j & 1);        // 0..7
        int aq = ((c >= 4) ? 2 : 0) + ((r >= 8) ? 1 : 0);
        int lp = ((r & 7) << 2) + (c & 3);
        hdst[((((ct << 3) + w) << 5) + lp) * 4 + aq] = tf32r(h);
    }
}

// ----------------------------- setup kernels -----------------------------
__device__ __forceinline__ float wfetch(const float* Wih, const float* Whh, int gr, int k,
                                        int kxt, int kxv) {
    if (k < kxt) return (k < kxv) ? Wih[gr * kxv + k] : 0.f;
    return Whh[gr * HIDQ + (k - kxt)];
}

__global__ void fmt_layer(int which, const float* __restrict__ Wih,
                          const float* __restrict__ Whh, int KS, int kxt, int kxv) {
    int idx = blockIdx.x * blockDim.x + threadIdx.x;
    if (idx >= NCTA * KS * 128) return;
    float2* dst = (which == 0) ? g_W1 : (which == 1) ? g_W2 : g_W3;
    int nt = idx & 3;
    int lane = (idx >> 2) & 31;
    int ks = (idx >> 7) % KS;
    int ct = idx / (KS * 128);
    int gr = nt * HIDQ + (ct << 3) + (lane >> 2);
    int k0 = (ks << 3) + (lane & 3);
    float v0 = wfetch(Wih, Whh, gr, k0, kxt, kxv);
    float v1 = wfetch(Wih, Whh, gr, k0 + 4, kxt, kxv);
    dst[(((size_t)ct * KS + ks) * 32 + lane) * 4 + nt] = make_float2(tf32r(v0), tf32r(v1));
}

__device__ __forceinline__ float ldx(const float* s, int b, int t, int f) {
    return (f < INF) ? tf32r(s[(b * TQ + t) * INF + f]) : 0.f;
}

// decoder weight fmt + x fmt merged
__global__ void fmt_dx(const float* __restrict__ Wdec, const float* __restrict__ seq) {
    int idx = blockIdx.x * blockDim.x + threadIdx.x;
    if (idx < DCTA * KSD * 32) {
        int lane = idx & 31;
        int ks = (idx >> 5) % KSD;
        int ct = idx / (KSD * 32);
        int orow = (ct << 3) + (lane >> 2);
        int k0 = (ks << 3) + (lane & 3);
        float v0 = (orow < OUTF) ? Wdec[orow * HIDQ + k0] : 0.f;
        float v1 = (orow < OUTF) ? Wdec[orow * HIDQ + k0 + 4] : 0.f;
        g_Wd[idx] = make_float2(tf32r(v0), tf32r(v1));
    }
    if (idx < TQ * KSX * 8 * 32) {
        int lane = idx & 31;
        int mt = (idx >> 5) & 7;
        int ks = (idx >> 8) % KSX;
        int t = idx / (KSX * 256);
        int r = lane >> 2, cc = lane & 3;
        int b0 = (mt << 4) + r;
        int f0 = (ks << 3) + cc;
        float4 v = make_float4(ldx(seq, b0, t, f0), ldx(seq, b0 + 8, t, f0),
                               ldx(seq, b0, t, f0 + 4), ldx(seq, b0 + 8, t, f0 + 4));
        ((float4*)g_xfrag)[idx] = v;
    }
}

// zero state + biases merged
__global__ void setup_misc(const float* bi1, const float* bh1, const float* bi2,
                           const float* bh2, const float* bi3, const float* bh3,
                           const float* bd) {
    int i = blockIdx.x * blockDim.x + threadIdx.x;
    if (i == 0) { g_cnt = 0u; g_gen = 0u; }
    if (i < 2 * HFR) { g_h1[i] = 0.f; g_h2[i] = 0.f; g_h3[i] = 0.f; }
    if (i < 2 * XFR) g_of[i] = 0.f;
    if (i < 4096) g_bias1[i] = bi1[i] + bh1[i];
    else if (i < 8192) { int k = i - 4096; g_bias2[k] = bi2[k] + bh2[k]; }
    else if (i < 12288) { int k = i - 8192; g_bias3[k] = bi3[k] + bh3[k]; }
    else if (i < 12288 + 176) { int oc = i - 12288; g_biasd[oc] = (oc < OUTF) ? bd[oc] : 0.f; }
}

// ----------------------------- persistent main kernel -----------------------------
__global__ void __launch_bounds__(NTHR, 1)
lstm_main(const int* __restrict__ pcn, const int* __restrict__ pgn, float* __restrict__ out) {
    int ct = blockIdx.x, tid = threadIdx.x, w = tid >> 5, lane = tid & 31;
    int cn = *pcn, gn = *pgn;
    int cyc = cn + gn;
    if (cyc <= 0) cyc = 1;
    float c1[4] = {0, 0, 0, 0}, c2[4] = {0, 0, 0, 0}, c3[4] = {0, 0, 0, 0};
    unsigned gen = 0;
    float acc[16];

    for (int t = 0; t < TQ; ++t) {
        int p = t & 1, q = p ^ 1;
        int use_gt = (t % cyc) < gn;
        const float* xsrc = use_gt ? (g_xfrag + (size_t)t * XFR) : (g_of + (size_t)q * XFR);

        // ---- layer 1: A = [x(256) | h0_prev(1024)] ----
        {
            const float4* wq = (const float4*)g_W1 + (size_t)ct * KS1 * 64;
            initacc(acc, g_bias1, ct, lane);
            mma_span(acc, xsrc, KSX, w, lane, wq);
            mma_span(acc, g_h1 + (size_t)q * HFR, KSH, w, lane, wq + (size_t)KSX * 64);
            lstm_epi(acc, c1, g_h1 + (size_t)p * HFR, ct, w, lane);
        }
        gen++; gridbar(gen);

        // ---- layer 2: A = [h0_cur | h1_prev] ----
        {
            const float4* wq = (const float4*)g_W2 + (size_t)ct * KS2 * 64;
            initacc(acc, g_bias2, ct, lane);
            mma_span(acc, g_h1 + (size_t)p * HFR, KSH, w, lane, wq);
            mma_span(acc, g_h2 + (size_t)q * HFR, KSH, w, lane, wq + (size_t)KSH * 64);
            lstm_epi(acc, c2, g_h2 + (size_t)p * HFR, ct, w, lane);
        }
        gen++; gridbar(gen);

        // ---- layer 3: A = [h1_cur | h2_prev] ----
        {
            const float4* wq = (const float4*)g_W3 + (size_t)ct * KS2 * 64;
            initacc(acc, g_bias3, ct, lane);
            mma_span(acc, g_h2 + (size_t)p * HFR, KSH, w, lane, wq);
            mma_span(acc, g_h3 + (size_t)q * HFR, KSH, w, lane, wq + (size_t)KSH * 64);
            lstm_epi(acc, c3, g_h3 + (size_t)p * HFR, ct, w, lane);
        }
        gen++; gridbar(gen);

        // ---- decoder (CTAs 0..21): out = h3 @ Wdec^T + b ----
        if (ct < DCTA) {
            float d0 = g_biasd[(ct << 3) + ((lane & 3) << 1)];
            float d1 = g_biasd[(ct << 3) + ((lane & 3) << 1) + 1];
            float dacc[4] = {d0, d1, d0, d1};
            const float2* wp = g_Wd + (size_t)ct * KSD * 32 + lane;
            const float4* A4 = (const float4*)(g_h3 + (size_t)p * HFR);
            float4 adb[8]; float2 wdb[8];
#pragma unroll
            for (int i = 0; i < 8; ++i) {
                adb[i] = __ldcg(A4 + (i * 8 + w) * 32 + lane);
                wdb[i] = wp[i * 32];
            }
#pragma unroll 8
            for (int ks = 0; ks < KSD; ++ks) {
                int s = ks & 7;
                float4 a = adb[s]; float2 b = wdb[s];
                int pf = ks + 8;
                if (pf < KSD) {
                    adb[s] = __ldcg(A4 + (pf * 8 + w) * 32 + lane);
                    wdb[s] = wp[pf * 32];
                }
                mma8(dacc, __float_as_uint(a.x), __float_as_uint(a.y), __float_as_uint(a.z),
                     __float_as_uint(a.w), __float_as_uint(b.x), __float_as_uint(b.y));
            }
            float* ofr = g_of + (size_t)p * XFR;
#pragma unroll
            for (int j = 0; j < 4; ++j) {
                int r = (lane >> 2) + ((j & 2) << 2);
                int c = ((lane & 3) << 1) + (j & 1);
                int b = (w << 4) + r;
                int oc = (ct << 3) + c;
                if (oc < OUTF) out[(b * TQ + t) * OUTF + oc] = dacc[j];
                int aq = ((c >= 4) ? 2 : 0) + ((r >= 8) ? 1 : 0);
                int lp = ((r & 7) << 2) + (c & 3);
                ofr[((((ct << 3) + w) << 5) + lp) * 4 + aq] = tf32r(dacc[j]);
            }
        }
        // 4th barrier only needed if next step reads decoder output (non-teacher-forced)
        int next_nontf = (t + 1 < TQ) && (((t + 1) % cyc) >= gn);
        if (next_nontf) { gen++; gridbar(gen); }
    }
}

// ----------------------------- launcher -----------------------------
extern "C" void kernel_launch(void* const* d_in, const int* in_sizes, int n_in,
                              void* d_out, int out_size) {
    const float* seq  = (const float*)d_in[0];
    const int*   pcn  = (const int*)d_in[1];
    const int*   pgn  = (const int*)d_in[2];
    const float* Wih1 = (const float*)d_in[3];
    const float* Whh1 = (const float*)d_in[4];
    const float* bih1 = (const float*)d_in[5];
    const float* bhh1 = (const float*)d_in[6];
    const float* Wih2 = (const float*)d_in[7];
    const float* Whh2 = (const float*)d_in[8];
    const float* bih2 = (const float*)d_in[9];
    const float* bhh2 = (const float*)d_in[10];
    const float* Wih3 = (const float*)d_in[11];
    const float* Whh3 = (const float*)d_in[12];
    const float* bih3 = (const float*)d_in[13];
    const float* bhh3 = (const float*)d_in[14];
    const float* Wdec = (const float*)d_in[15];
    const float* bdec = (const float*)d_in[16];

    // 5 setup launches, then lstm_main at launch index 5 (ncu -s 5 -c 1 captures it)
    setup_misc<<<(2 * HFR + 255) / 256, 256>>>(bih1, bhh1, bih2, bhh2, bih3, bhh3, bdec);
    fmt_layer<<<(NCTA * KS1 * 128 + 255) / 256, 256>>>(0, Wih1, Whh1, KS1, 8 * KSX, INF);
    fmt_layer<<<(NCTA * KS2 * 128 + 255) / 256, 256>>>(1, Wih2, Whh2, KS2, 1024, 1024);
    fmt_layer<<<(NCTA * KS2 * 128 + 255) / 256, 256>>>(2, Wih3, Whh3, KS2, 1024, 1024);
    fmt_dx<<<(TQ * KSX * 256 + 255) / 256, 256>>>(Wdec, seq);
    lstm_main<<<NCTA, NTHR>>>(pcn, pgn, (float*)d_out);
}

// round 7
// speedup vs baseline: 2.1841x; 1.0236x over previous
#include <cuda_runtime.h>
#include <cstdint>

#define NCTA 128
#define NTHR 256
#define TQ   200
#define INF  171
#define OUTF 171
#define HIDQ 1024
#define KSX  32            // x-part k-steps (256 padded cols)
#define KSH  128           // h-part k-steps (1024 cols)
#define KS1  (KSX + KSH)   // 160
#define KS2  (2 * KSH)     // 256
#define KSD  KSH
#define DCTA 22
#define HFR  (KSH * 1024)  // floats per parity of an h activation buffer
#define XFR  (KSX * 1024)  // floats per x/out fragment block
#define CHKS 16            // k-steps per weight chunk
#define CHB  (CHKS * 1024) // 16 KB chunk bytes

// ------------------- persistent device state (static, no allocs) -------------------
__device__ __align__(16) float2 g_W1[NCTA * KS1 * 128];      // 21 MB   per-ks plane layout
__device__ __align__(16) float2 g_W2[NCTA * KS2 * 128];      // 33.6 MB
__device__ __align__(16) float2 g_W3[NCTA * KS2 * 128];      // 33.6 MB
__device__ __align__(16) float2 g_Wd[DCTA * KSD * 32];       // 0.7 MB
__device__ float g_bias1[4 * HIDQ];
__device__ float g_bias2[4 * HIDQ];
__device__ float g_bias3[4 * HIDQ];
__device__ float g_biasd[176];
__device__ __align__(16) float g_xfrag[TQ * XFR];            // 26 MB: real_seq pre-formatted
__device__ __align__(16) float g_h1[2 * HFR];
__device__ __align__(16) float g_h2[2 * HFR];
__device__ __align__(16) float g_h3[2 * HFR];
__device__ __align__(16) float g_of[2 * XFR];                // decoder out fragments
__device__ unsigned g_cnt;
__device__ volatile unsigned g_gen;

// ----------------------------- small helpers -----------------------------
__device__ __forceinline__ float tf32r(float x) {
    uint32_t y;
    asm("cvt.rna.tf32.f32 %0, %1;" : "=r"(y) : "f"(x));
    return __uint_as_float(y);
}

__device__ __forceinline__ void mma8(float* c, uint32_t a0, uint32_t a1, uint32_t a2,
                                     uint32_t a3, uint32_t b0, uint32_t b1) {
    asm("mma.sync.aligned.m16n8k8.row.col.f32.tf32.tf32.f32 "
        "{%0,%1,%2,%3},{%4,%5,%6,%7},{%8,%9},{%0,%1,%2,%3};"
        : "+f"(c[0]), "+f"(c[1]), "+f"(c[2]), "+f"(c[3])
        : "r"(a0), "r"(a1), "r"(a2), "r"(a3), "r"(b0), "r"(b1));
}

__device__ __forceinline__ float sigm(float x) { return 1.f / (1.f + __expf(-x)); }

__device__ __forceinline__ uint32_t smem_u32(const void* p) {
    return (uint32_t)__cvta_generic_to_shared(p);
}
__device__ __forceinline__ void mbar_init(uint32_t a, uint32_t cnt) {
    asm volatile("mbarrier.init.shared.b64 [%0], %1;" :: "r"(a), "r"(cnt) : "memory");
}
__device__ __forceinline__ void mbar_expect_tx(uint32_t a, uint32_t bytes) {
    asm volatile("mbarrier.arrive.expect_tx.shared.b64 _, [%0], %1;"
                 :: "r"(a), "r"(bytes) : "memory");
}
__device__ __forceinline__ void bulk_g2s(uint32_t dst, const void* src, uint32_t bytes,
                                         uint32_t mbar) {
    asm volatile("cp.async.bulk.shared::cta.global.mbarrier::complete_tx::bytes "
                 "[%0], [%1], %2, [%3];"
                 :: "r"(dst), "l"(src), "r"(bytes), "r"(mbar) : "memory");
}
__device__ __forceinline__ void mbar_wait(uint32_t a, int parity) {
    asm volatile(
        "{\n\t.reg .pred P;\n\t"
        "WL%=:\n\t"
        "mbarrier.try_wait.parity.acquire.cta.shared::cta.b64 P, [%0], %1, 0x989680;\n\t"
        "@!P bra WL%=;\n\t}"
        :: "r"(a), "r"(parity) : "memory");
}
__device__ __forceinline__ float4 lds128(uint32_t a) {
    float4 v;
    asm volatile("ld.shared.v4.f32 {%0,%1,%2,%3}, [%4];"
                 : "=f"(v.x), "=f"(v.y), "=f"(v.z), "=f"(v.w) : "r"(a));
    return v;
}

// grid-wide spin barrier (all 128 CTAs resident: 1 CTA/SM)
__device__ __forceinline__ void gridbar(unsigned gen) {
    __syncthreads();
    if (threadIdx.x == 0) {
        __threadfence();
        unsigned arr = atomicAdd(&g_cnt, 1u);
        if (arr == NCTA - 1u) {
            g_cnt = 0u;
            __threadfence();
            g_gen = gen;
        } else {
            while (g_gen != gen) { __nanosleep(32); }
        }
        __threadfence();
    }
    __syncthreads();
}

__device__ __forceinline__ void initacc(float acc[16], const float* bias, int ct, int lane) {
#pragma unroll
    for (int nt = 0; nt < 4; ++nt) {
        int col = nt * HIDQ + (ct << 3) + ((lane & 3) << 1);
        float b0 = bias[col], b1 = bias[col + 1];
        acc[4 * nt] = b0; acc[4 * nt + 1] = b1;
        acc[4 * nt + 2] = b0; acc[4 * nt + 3] = b1;
    }
}

// one layer: A = [A0(nks0 ks) | A1(KS-nks0 ks)], W streamed to smem in 16-ks chunks.
// A in fragment layout [ks][mt=8][lane]{float4} read via depth-8 __ldcg ring.
// W smem chunk layout per ks: [w0: 32 lanes x 16B][w1: 32 lanes x 16B] = 1 KB.
__device__ __forceinline__ void layer_mm(float acc[16], const float* A0, int nks0,
                                         const float* A1, int KS, const char* wsrc,
                                         const uint32_t wsm[2], const uint32_t mb[2],
                                         int ph[2], int tid, int w, int lane) {
    const float4* A04 = (const float4*)A0;
    const float4* A14 = (const float4*)A1;
    float4 ab[8];
#pragma unroll
    for (int i = 0; i < 8; ++i)            // nks0 >= 32 always, so first 8 come from A0
        ab[i] = __ldcg(A04 + (i * 8 + w) * 32 + lane);

    int nch = KS >> 4;
    if (tid == 0) {
        mbar_expect_tx(mb[0], CHB);
        bulk_g2s(wsm[0], wsrc, CHB, mb[0]);
    }
    for (int c = 0; c < nch; ++c) {
        __syncthreads();   // previous chunk in buffer (c+1)&1 fully consumed by all warps
        if (tid == 0 && c + 1 < nch) {
            int b1 = (c + 1) & 1;
            mbar_expect_tx(mb[b1], CHB);
            bulk_g2s(wsm[b1], wsrc + (size_t)(c + 1) * CHB, CHB, mb[b1]);
        }
        int b = c & 1;
        mbar_wait(mb[b], ph[b]);
        ph[b] ^= 1;
        uint32_t wbase = wsm[b] + (lane << 4);
#pragma unroll
        for (int j = 0; j < 16; ++j) {
            int ks = (c << 4) + j;
            int s = ks & 7;
            float4 a = ab[s];
            int pf = ks + 8;
            if (pf < KS) {
                const float4* src = (pf < nks0) ? (A04 + (pf * 8 + w) * 32)
                                                : (A14 + ((pf - nks0) * 8 + w) * 32);
                ab[s] = __ldcg(src + lane);
            }
            float4 w0 = lds128(wbase + j * 1024);
            float4 w1 = lds128(wbase + j * 1024 + 512);
            uint32_t a0 = __float_as_uint(a.x), a1 = __float_as_uint(a.y);
            uint32_t a2 = __float_as_uint(a.z), a3 = __float_as_uint(a.w);
            mma8(acc + 0,  a0, a1, a2, a3, __float_as_uint(w0.x), __float_as_uint(w0.y));
            mma8(acc + 4,  a0, a1, a2, a3, __float_as_uint(w0.z), __float_as_uint(w0.w));
            mma8(acc + 8,  a0, a1, a2, a3, __float_as_uint(w1.x), __float_as_uint(w1.y));
            mma8(acc + 12, a0, a1, a2, a3, __float_as_uint(w1.z), __float_as_uint(w1.w));
        }
    }
}

// LSTM cell epilogue: gates -> c,h; scatter h into fragment layout for next consumers
__device__ __forceinline__ void lstm_epi(const float acc[16], float cst[4], float* hdst,
                                         int ct, int w, int lane) {
#pragma unroll
    for (int j = 0; j < 4; ++j) {
        float ig = sigm(acc[0 + j]);
        float fg = sigm(acc[4 + j]);
        float gg = tanhf(acc[8 + j]);
        float og = sigm(acc[12 + j]);
        float cc = fg * cst[j] + ig * gg;
        cst[j] = cc;
        float h = og * tanhf(cc);
        int r = (lane >> 2) + ((j & 2) << 2);       // 0..15
        int c = ((lane & 3) << 1) + (j & 1);        // 0..7
        int aq = ((c >= 4) ? 2 : 0) + ((r >= 8) ? 1 : 0);
        int lp = ((r & 7) << 2) + (c & 3);
        hdst[((((ct << 3) + w) << 5) + lp) * 4 + aq] = tf32r(h);
    }
}

// ----------------------------- setup kernels (2 launches) -----------------------------
__device__ __forceinline__ float wfetch(const float* Wih, const float* Whh, int gr, int k,
                                        int kxt, int kxv) {
    if (k < kxt) return (k < kxv) ? Wih[gr * kxv + k] : 0.f;
    return Whh[gr * HIDQ + (k - kxt)];
}

__device__ __forceinline__ void fmt_one(float2* dst, const float* Wih, const float* Whh,
                                        int KS, int kxt, int kxv, int idx) {
    int nt = idx & 3;
    int lane = (idx >> 2) & 31;
    int ks = (idx >> 7) % KS;
    int ct = idx / (KS * 128);
    int gr = nt * HIDQ + (ct << 3) + (lane >> 2);
    int k0 = (ks << 3) + (lane & 3);
    float v0 = wfetch(Wih, Whh, gr, k0, kxt, kxv);
    float v1 = wfetch(Wih, Whh, gr, k0 + 4, kxt, kxv);
    // plane layout: per ks 1KB = [nt01: lane*16B][nt23: lane*16B]
    size_t off = ((size_t)ct * KS + ks) * 128 + (nt >> 1) * 64 + lane * 2 + (nt & 1);
    dst[off] = make_float2(tf32r(v0), tf32r(v1));
}

__global__ void fmt_layers(const float* __restrict__ Wih1, const float* __restrict__ Whh1,
                           const float* __restrict__ Wih2, const float* __restrict__ Whh2,
                           const float* __restrict__ Wih3, const float* __restrict__ Whh3) {
    int idx = blockIdx.x * blockDim.x + threadIdx.x;
    const int n1 = NCTA * KS1 * 128;
    const int n2 = NCTA * KS2 * 128;
    if (idx < n1) { fmt_one(g_W1, Wih1, Whh1, KS1, 8 * KSX, INF, idx); return; }
    idx -= n1;
    if (idx < n2) { fmt_one(g_W2, Wih2, Whh2, KS2, 1024, 1024, idx); return; }
    idx -= n2;
    if (idx < n2) { fmt_one(g_W3, Wih3, Whh3, KS2, 1024, 1024, idx); return; }
}

__device__ __forceinline__ float ldx(const float* s, int b, int t, int f) {
    return (f < INF) ? tf32r(s[(b * TQ + t) * INF + f]) : 0.f;
}

// zero state + biases + decoder W fmt + x fmt, all in one launch
__global__ void setup_all(const float* bi1, const float* bh1, const float* bi2,
                          const float* bh2, const float* bi3, const float* bh3,
                          const float* bd, const float* __restrict__ Wdec,
                          const float* __restrict__ seq) {
    int i = blockIdx.x * blockDim.x + threadIdx.x;
    if (i == 0) { g_cnt = 0u; g_gen = 0u; }
    if (i < 2 * HFR) { g_h1[i] = 0.f; g_h2[i] = 0.f; g_h3[i] = 0.f; }
    if (i < 2 * XFR) g_of[i] = 0.f;
    if (i < 4096) g_bias1[i] = bi1[i] + bh1[i];
    else if (i < 8192) { int k = i - 4096; g_bias2[k] = bi2[k] + bh2[k]; }
    else if (i < 12288) { int k = i - 8192; g_bias3[k] = bi3[k] + bh3[k]; }
    else if (i < 12288 + 176) { int oc = i - 12288; g_biasd[oc] = (oc < OUTF) ? bd[oc] : 0.f; }
    if (i < DCTA * KSD * 32) {
        int lane = i & 31;
        int ks = (i >> 5) % KSD;
        int ct = i / (KSD * 32);
        int orow = (ct << 3) + (lane >> 2);
        int k0 = (ks << 3) + (lane & 3);
        float v0 = (orow < OUTF) ? Wdec[orow * HIDQ + k0] : 0.f;
        float v1 = (orow < OUTF) ? Wdec[orow * HIDQ + k0 + 4] : 0.f;
        g_Wd[i] = make_float2(tf32r(v0), tf32r(v1));
    }
    if (i < TQ * KSX * 8 * 32) {
        int lane = i & 31;
        int mt = (i >> 5) & 7;
        int ks = (i >> 8) % KSX;
        int t = i / (KSX * 256);
        int r = lane >> 2, cc = lane & 3;
        int b0 = (mt << 4) + r;
        int f0 = (ks << 3) + cc;
        float4 v = make_float4(ldx(seq, b0, t, f0), ldx(seq, b0 + 8, t, f0),
                               ldx(seq, b0, t, f0 + 4), ldx(seq, b0 + 8, t, f0 + 4));
        ((float4*)g_xfrag)[i] = v;
    }
}

// ----------------------------- persistent main kernel -----------------------------
__global__ void __launch_bounds__(NTHR, 1)
lstm_main(const int* __restrict__ pcn, const int* __restrict__ pgn, float* __restrict__ out) {
    __shared__ __align__(16) char wbuf[2][CHB];
    __shared__ __align__(8) unsigned long long s_mbar[2];

    int ct = blockIdx.x, tid = threadIdx.x, w = tid >> 5, lane = tid & 31;
    uint32_t wsm[2] = { smem_u32(wbuf[0]), smem_u32(wbuf[1]) };
    uint32_t mb[2]  = { smem_u32(&s_mbar[0]), smem_u32(&s_mbar[1]) };
    if (tid == 0) { mbar_init(mb[0], 1); mbar_init(mb[1], 1); }
    __syncthreads();
    int ph[2] = {0, 0};

    int cn = *pcn, gn = *pgn;
    int cyc = cn + gn;
    if (cyc <= 0) cyc = 1;
    float c1[4] = {0, 0, 0, 0}, c2[4] = {0, 0, 0, 0}, c3[4] = {0, 0, 0, 0};
    unsigned gen = 0;
    float acc[16];

    const char* w1src = (const char*)(g_W1 + (size_t)ct * KS1 * 128);
    const char* w2src = (const char*)(g_W2 + (size_t)ct * KS2 * 128);
    const char* w3src = (const char*)(g_W3 + (size_t)ct * KS2 * 128);

    for (int t = 0; t < TQ; ++t) {
        int p = t & 1, q = p ^ 1;
        int use_gt = (t % cyc) < gn;
        const float* xsrc = use_gt ? (g_xfrag + (size_t)t * XFR) : (g_of + (size_t)q * XFR);

        // ---- layer 1: A = [x(256) | h1_prev(1024)] ----
        initacc(acc, g_bias1, ct, lane);
        layer_mm(acc, xsrc, KSX, g_h1 + (size_t)q * HFR, KS1, w1src, wsm, mb, ph, tid, w, lane);
        lstm_epi(acc, c1, g_h1 + (size_t)p * HFR, ct, w, lane);
        gen++; gridbar(gen);

        // ---- layer 2: A = [h1_cur | h2_prev] ----
        initacc(acc, g_bias2, ct, lane);
        layer_mm(acc, g_h1 + (size_t)p * HFR, KSH, g_h2 + (size_t)q * HFR, KS2, w2src,
                 wsm, mb, ph, tid, w, lane);
        lstm_epi(acc, c2, g_h2 + (size_t)p * HFR, ct, w, lane);
        gen++; gridbar(gen);

        // ---- layer 3: A = [h2_cur | h3_prev] ----
        initacc(acc, g_bias3, ct, lane);
        layer_mm(acc, g_h2 + (size_t)p * HFR, KSH, g_h3 + (size_t)q * HFR, KS2, w3src,
                 wsm, mb, ph, tid, w, lane);
        lstm_epi(acc, c3, g_h3 + (size_t)p * HFR, ct, w, lane);
        gen++; gridbar(gen);

        // ---- decoder (CTAs 0..21): out = h3 @ Wdec^T + b ----
        if (ct < DCTA) {
            float d0 = g_biasd[(ct << 3) + ((lane & 3) << 1)];
            float d1 = g_biasd[(ct << 3) + ((lane & 3) << 1) + 1];
            float dacc[4] = {d0, d1, d0, d1};
            const float2* wp = g_Wd + (size_t)ct * KSD * 32 + lane;
            const float4* A4 = (const float4*)(g_h3 + (size_t)p * HFR);
            float4 adb[8]; float2 wdb[8];
#pragma unroll
            for (int i = 0; i < 8; ++i) {
                adb[i] = __ldcg(A4 + (i * 8 + w) * 32 + lane);
                wdb[i] = wp[i * 32];
            }
#pragma unroll 8
            for (int ks = 0; ks < KSD; ++ks) {
                int s = ks & 7;
                float4 a = adb[s]; float2 b = wdb[s];
                int pf = ks + 8;
                if (pf < KSD) {
                    adb[s] = __ldcg(A4 + (pf * 8 + w) * 32 + lane);
                    wdb[s] = wp[pf * 32];
                }
                mma8(dacc, __float_as_uint(a.x), __float_as_uint(a.y), __float_as_uint(a.z),
                     __float_as_uint(a.w), __float_as_uint(b.x), __float_as_uint(b.y));
            }
            float* ofr = g_of + (size_t)p * XFR;
#pragma unroll
            for (int j = 0; j < 4; ++j) {
                int r = (lane >> 2) + ((j & 2) << 2);
                int c = ((lane & 3) << 1) + (j & 1);
                int b = (w << 4) + r;
                int oc = (ct << 3) + c;
                if (oc < OUTF) out[(b * TQ + t) * OUTF + oc] = dacc[j];
                int aq = ((c >= 4) ? 2 : 0) + ((r >= 8) ? 1 : 0);
                int lp = ((r & 7) << 2) + (c & 3);
                ofr[((((ct << 3) + w) << 5) + lp) * 4 + aq] = tf32r(dacc[j]);
            }
        }
        // 4th barrier only needed if next step reads decoder output (non-teacher-forced)
        int next_nontf = (t + 1 < TQ) && (((t + 1) % cyc) >= gn);
        if (next_nontf) { gen++; gridbar(gen); }
    }
}

// ----------------------------- launcher -----------------------------
extern "C" void kernel_launch(void* const* d_in, const int* in_sizes, int n_in,
                              void* d_out, int out_size) {
    const float* seq  = (const float*)d_in[0];
    const int*   pcn  = (const int*)d_in[1];
    const int*   pgn  = (const int*)d_in[2];
    const float* Wih1 = (const float*)d_in[3];
    const float* Whh1 = (const float*)d_in[4];
    const float* bih1 = (const float*)d_in[5];
    const float* bhh1 = (const float*)d_in[6];
    const float* Wih2 = (const float*)d_in[7];
    const float* Whh2 = (const float*)d_in[8];
    const float* bih2 = (const float*)d_in[9];
    const float* bhh2 = (const float*)d_in[10];
    const float* Wih3 = (const float*)d_in[11];
    const float* Whh3 = (const float*)d_in[12];
    const float* bih3 = (const float*)d_in[13];
    const float* bhh3 = (const float*)d_in[14];
    const float* Wdec = (const float*)d_in[15];
    const float* bdec = (const float*)d_in[16];

    // 2 setup launches, then lstm_main
    setup_all<<<(TQ * KSX * 256 + 255) / 256, 256>>>(bih1, bhh1, bih2, bhh2, bih3, bhh3,
                                                     bdec, Wdec, seq);
    {
        int total = NCTA * (KS1 + KS2 + KS2) * 128;
        fmt_layers<<<(total + 255) / 256, 256>>>(Wih1, Whh1, Wih2, Whh2, Wih3, Whh3);
    }
    lstm_main<<<NCTA, NTHR>>>(pcn, pgn, (float*)d_out);
}

// round 8
// speedup vs baseline: 2.2009x; 1.0077x over previous
#include <cuda_runtime.h>
#include <cstdint>

#define NCTA 128
#define NTHR 256
#define TQ   200
#define INF  171
#define OUTF 171
#define HIDQ 1024
#define KSX  32            // x-part k-steps (256 padded cols)
#define KSH  128           // h-part k-steps (1024 cols)
#define KS1  (KSX + KSH)   // 160
#define KS2  (2 * KSH)     // 256
#define KSD  KSH
#define DCTA 22
#define HFR  (KSH * 1024)  // floats per parity of an h activation buffer
#define XFR  (KSX * 1024)  // floats per x/out fragment block
#define CHKS 16            // k-steps per weight chunk
#define CHB  (CHKS * 1024) // 16 KB chunk bytes

// ------------------- persistent device state (static, no allocs) -------------------
__device__ __align__(16) float2 g_W1[NCTA * KS1 * 128];      // 21 MB   per-ks plane layout
__device__ __align__(16) float2 g_W2[NCTA * KS2 * 128];      // 33.6 MB
__device__ __align__(16) float2 g_W3[NCTA * KS2 * 128];      // 33.6 MB
__device__ __align__(16) float2 g_Wd[DCTA * KSD * 32];       // 0.7 MB
__device__ float g_bias1[4 * HIDQ];
__device__ float g_bias2[4 * HIDQ];
__device__ float g_bias3[4 * HIDQ];
__device__ float g_biasd[176];
__device__ __align__(16) float g_xfrag[TQ * XFR];            // 26 MB: real_seq pre-formatted
__device__ __align__(16) float g_h1[2 * HFR];
__device__ __align__(16) float g_h2[2 * HFR];
__device__ __align__(16) float g_h3[2 * HFR];
__device__ __align__(16) float g_of[2 * XFR];                // decoder out fragments
__device__ unsigned g_cnt;
__device__ volatile unsigned g_gen;

// ----------------------------- small helpers -----------------------------
__device__ __forceinline__ float tf32r(float x) {
    uint32_t y;
    asm("cvt.rna.tf32.f32 %0, %1;" : "=r"(y) : "f"(x));
    return __uint_as_float(y);
}

__device__ __forceinline__ void mma8(float* c, uint32_t a0, uint32_t a1, uint32_t a2,
                                     uint32_t a3, uint32_t b0, uint32_t b1) {
    asm("mma.sync.aligned.m16n8k8.row.col.f32.tf32.tf32.f32 "
        "{%0,%1,%2,%3},{%4,%5,%6,%7},{%8,%9},{%0,%1,%2,%3};"
        : "+f"(c[0]), "+f"(c[1]), "+f"(c[2]), "+f"(c[3])
        : "r"(a0), "r"(a1), "r"(a2), "r"(a3), "r"(b0), "r"(b1));
}

__device__ __forceinline__ float sigm(float x) { return 1.f / (1.f + __expf(-x)); }

__device__ __forceinline__ uint32_t smem_u32(const void* p) {
    return (uint32_t)__cvta_generic_to_shared(p);
}
__device__ __forceinline__ void mbar_init(uint32_t a, uint32_t cnt) {
    asm volatile("mbarrier.init.shared.b64 [%0], %1;" :: "r"(a), "r"(cnt) : "memory");
}
__device__ __forceinline__ void mbar_expect_tx(uint32_t a, uint32_t bytes) {
    asm volatile("mbarrier.arrive.expect_tx.shared.b64 _, [%0], %1;"
                 :: "r"(a), "r"(bytes) : "memory");
}
__device__ __forceinline__ void bulk_g2s(uint32_t dst, const void* src, uint32_t bytes,
                                         uint32_t mbar) {
    asm volatile("cp.async.bulk.shared::cta.global.mbarrier::complete_tx::bytes "
                 "[%0], [%1], %2, [%3];"
                 :: "r"(dst), "l"(src), "r"(bytes), "r"(mbar) : "memory");
}
__device__ __forceinline__ void mbar_wait(uint32_t a, int parity) {
    asm volatile(
        "{\n\t.reg .pred P;\n\t"
        "WL%=:\n\t"
        "mbarrier.try_wait.parity.acquire.cta.shared::cta.b64 P, [%0], %1, 0x989680;\n\t"
        "@!P bra WL%=;\n\t}"
        :: "r"(a), "r"(parity) : "memory");
}
__device__ __forceinline__ float4 lds128(uint32_t a) {
    float4 v;
    asm volatile("ld.shared.v4.f32 {%0,%1,%2,%3}, [%4];"
                 : "=f"(v.x), "=f"(v.y), "=f"(v.z), "=f"(v.w) : "r"(a));
    return v;
}

// grid-wide spin barrier (all 128 CTAs resident: 1 CTA/SM)
__device__ __forceinline__ void gridbar(unsigned gen) {
    __syncthreads();
    if (threadIdx.x == 0) {
        __threadfence();
        unsigned arr = atomicAdd(&g_cnt, 1u);
        if (arr == NCTA - 1u) {
            g_cnt = 0u;
            __threadfence();
            g_gen = gen;
        } else {
            while (g_gen != gen) { __nanosleep(32); }
        }
        __threadfence();
    }
    __syncthreads();
}

__device__ __forceinline__ void initacc(float acc[16], const float* bias, int ct, int lane) {
#pragma unroll
    for (int nt = 0; nt < 4; ++nt) {
        int col = nt * HIDQ + (ct << 3) + ((lane & 3) << 1);
        float b0 = bias[col], b1 = bias[col + 1];
        acc[4 * nt] = b0; acc[4 * nt + 1] = b1;
        acc[4 * nt + 2] = b0; acc[4 * nt + 3] = b1;
    }
}

// one layer: A = [A0(nks0 ks) | A1(KS-nks0 ks)], W streamed to smem in 16-ks chunks.
// A in fragment layout [ks][mt=8][lane]{float4} read via depth-8 __ldcg ring.
// W smem chunk layout per ks: [w0: 32 lanes x 16B][w1: 32 lanes x 16B] = 1 KB.
__device__ __forceinline__ void layer_mm(float acc[16], const float* A0, int nks0,
                                         const float* A1, int KS, const char* wsrc,
                                         const uint32_t wsm[2], const uint32_t mb[2],
                                         int ph[2], int tid, int w, int lane) {
    const float4* A04 = (const float4*)A0;
    const float4* A14 = (const float4*)A1;
    float4 ab[8];
#pragma unroll
    for (int i = 0; i < 8; ++i)            // nks0 >= 32 always, so first 8 come from A0
        ab[i] = __ldcg(A04 + (i * 8 + w) * 32 + lane);

    int nch = KS >> 4;
    if (tid == 0) {
        mbar_expect_tx(mb[0], CHB);
        bulk_g2s(wsm[0], wsrc, CHB, mb[0]);
    }
    for (int c = 0; c < nch; ++c) {
        __syncthreads();   // previous chunk in buffer (c+1)&1 fully consumed by all warps
        if (tid == 0 && c + 1 < nch) {
            int b1 = (c + 1) & 1;
            mbar_expect_tx(mb[b1], CHB);
            bulk_g2s(wsm[b1], wsrc + (size_t)(c + 1) * CHB, CHB, mb[b1]);
        }
        int b = c & 1;
        mbar_wait(mb[b], ph[b]);
        ph[b] ^= 1;
        uint32_t wbase = wsm[b] + (lane << 4);
#pragma unroll
        for (int j = 0; j < 16; ++j) {
            int ks = (c << 4) + j;
            int s = ks & 7;
            float4 a = ab[s];
            int pf = ks + 8;
            if (pf < KS) {
                const float4* src = (pf < nks0) ? (A04 + (pf * 8 + w) * 32)
                                                : (A14 + ((pf - nks0) * 8 + w) * 32);
                ab[s] = __ldcg(src + lane);
            }
            float4 w0 = lds128(wbase + j * 1024);
            float4 w1 = lds128(wbase + j * 1024 + 512);
            uint32_t a0 = __float_as_uint(a.x), a1 = __float_as_uint(a.y);
            uint32_t a2 = __float_as_uint(a.z), a3 = __float_as_uint(a.w);
            mma8(acc + 0,  a0, a1, a2, a3, __float_as_uint(w0.x), __float_as_uint(w0.y));
            mma8(acc + 4,  a0, a1, a2, a3, __float_as_uint(w0.z), __float_as_uint(w0.w));
            mma8(acc + 8,  a0, a1, a2, a3, __float_as_uint(w1.x), __float_as_uint(w1.y));
            mma8(acc + 12, a0, a1, a2, a3, __float_as_uint(w1.z), __float_as_uint(w1.w));
        }
    }
}

// LSTM cell epilogue: gates -> c,h; scatter h into fragment layout for next consumers
__device__ __forceinline__ void lstm_epi(const float acc[16], float cst[4], float* hdst,
                                         int ct, int w, int lane) {
#pragma unroll
    for (int j = 0; j < 4; ++j) {
        float ig = sigm(acc[0 + j]);
        float fg = sigm(acc[4 + j]);
        float gg = tanhf(acc[8 + j]);
        float og = sigm(acc[12 + j]);
        float cc = fg * cst[j] + ig * gg;
        cst[j] = cc;
        float h = og * tanhf(cc);
        int r = (lane >> 2) + ((j & 2) << 2);       // 0..15
        int c = ((lane & 3) << 1) + (j & 1);        // 0..7
        int aq = ((c >= 4) ? 2 : 0) + ((r >= 8) ? 1 : 0);
        int lp = ((r & 7) << 2) + (c & 3);
        hdst[((((ct << 3) + w) << 5) + lp) * 4 + aq] = tf32r(h);
    }
}

// ----------------------------- setup kernels (2 launches) -----------------------------
__device__ __forceinline__ float wfetch(const float* Wih, const float* Whh, int gr, int k,
                                        int kxt, int kxv) {
    if (k < kxt) return (k < kxv) ? Wih[gr * kxv + k] : 0.f;
    return Whh[gr * HIDQ + (k - kxt)];
}

__device__ __forceinline__ void fmt_one(float2* dst, const float* Wih, const float* Whh,
                                        int KS, int kxt, int kxv, int idx) {
    int nt = idx & 3;
    int lane = (idx >> 2) & 31;
    int ks = (idx >> 7) % KS;
    int ct = idx / (KS * 128);
    int gr = nt * HIDQ + (ct << 3) + (lane >> 2);
    int k0 = (ks << 3) + (lane & 3);
    float v0 = wfetch(Wih, Whh, gr, k0, kxt, kxv);
    float v1 = wfetch(Wih, Whh, gr, k0 + 4, kxt, kxv);
    // plane layout: per ks 1KB = [nt01: lane*16B][nt23: lane*16B]
    size_t off = ((size_t)ct * KS + ks) * 128 + (nt >> 1) * 64 + lane * 2 + (nt & 1);
    dst[off] = make_float2(tf32r(v0), tf32r(v1));
}

__global__ void fmt_layers(const float* __restrict__ Wih1, const float* __restrict__ Whh1,
                           const float* __restrict__ Wih2, const float* __restrict__ Whh2,
                           const float* __restrict__ Wih3, const float* __restrict__ Whh3) {
    int idx = blockIdx.x * blockDim.x + threadIdx.x;
    const int n1 = NCTA * KS1 * 128;
    const int n2 = NCTA * KS2 * 128;
    if (idx < n1) { fmt_one(g_W1, Wih1, Whh1, KS1, 8 * KSX, INF, idx); return; }
    idx -= n1;
    if (idx < n2) { fmt_one(g_W2, Wih2, Whh2, KS2, 1024, 1024, idx); return; }
    idx -= n2;
    if (idx < n2) { fmt_one(g_W3, Wih3, Whh3, KS2, 1024, 1024, idx); return; }
}

__device__ __forceinline__ float ldx(const float* s, int b, int t, int f) {
    return (f < INF) ? tf32r(s[(b * TQ + t) * INF + f]) : 0.f;
}

// zero state + biases + decoder W fmt + x fmt, all in one launch
__global__ void setup_all(const float* bi1, const float* bh1, const float* bi2,
                          const float* bh2, const float* bi3, const float* bh3,
                          const float* bd, const float* __restrict__ Wdec,
                          const float* __restrict__ seq) {
    int i = blockIdx.x * blockDim.x + threadIdx.x;
    if (i == 0) { g_cnt = 0u; g_gen = 0u; }
    if (i < 2 * HFR) { g_h1[i] = 0.f; g_h2[i] = 0.f; g_h3[i] = 0.f; }
    if (i < 2 * XFR) g_of[i] = 0.f;
    if (i < 4096) g_bias1[i] = bi1[i] + bh1[i];
    else if (i < 8192) { int k = i - 4096; g_bias2[k] = bi2[k] + bh2[k]; }
    else if (i < 12288) { int k = i - 8192; g_bias3[k] = bi3[k] + bh3[k]; }
    else if (i < 12288 + 176) { int oc = i - 12288; g_biasd[oc] = (oc < OUTF) ? bd[oc] : 0.f; }
    if (i < DCTA * KSD * 32) {
        int lane = i & 31;
        int ks = (i >> 5) % KSD;
        int ct = i / (KSD * 32);
        int orow = (ct << 3) + (lane >> 2);
        int k0 = (ks << 3) + (lane & 3);
        float v0 = (orow < OUTF) ? Wdec[orow * HIDQ + k0] : 0.f;
        float v1 = (orow < OUTF) ? Wdec[orow * HIDQ + k0 + 4] : 0.f;
        g_Wd[i] = make_float2(tf32r(v0), tf32r(v1));
    }
    if (i < TQ * KSX * 8 * 32) {
        int lane = i & 31;
        int mt = (i >> 5) & 7;
        int ks = (i >> 8) % KSX;
        int t = i / (KSX * 256);
        int r = lane >> 2, cc = lane & 3;
        int b0 = (mt << 4) + r;
        int f0 = (ks << 3) + cc;
        float4 v = make_float4(ldx(seq, b0, t, f0), ldx(seq, b0 + 8, t, f0),
                               ldx(seq, b0, t, f0 + 4), ldx(seq, b0 + 8, t, f0 + 4));
        ((float4*)g_xfrag)[i] = v;
    }
}

// ----------------------------- persistent main kernel -----------------------------
__global__ void __launch_bounds__(NTHR, 1)
lstm_main(const int* __restrict__ pcn, const int* __restrict__ pgn, float* __restrict__ out) {
    __shared__ __align__(16) char wbuf[2][CHB];
    __shared__ __align__(8) unsigned long long s_mbar[2];

    int ct = blockIdx.x, tid = threadIdx.x, w = tid >> 5, lane = tid & 31;
    uint32_t wsm[2] = { smem_u32(wbuf[0]), smem_u32(wbuf[1]) };
    uint32_t mb[2]  = { smem_u32(&s_mbar[0]), smem_u32(&s_mbar[1]) };
    if (tid == 0) { mbar_init(mb[0], 1); mbar_init(mb[1], 1); }
    __syncthreads();
    int ph[2] = {0, 0};

    int cn = *pcn, gn = *pgn;
    int cyc = cn + gn;
    if (cyc <= 0) cyc = 1;
    float c1[4] = {0, 0, 0, 0}, c2[4] = {0, 0, 0, 0}, c3[4] = {0, 0, 0, 0};
    unsigned gen = 0;
    float acc[16];

    const char* w1src = (const char*)(g_W1 + (size_t)ct * KS1 * 128);
    const char* w2src = (const char*)(g_W2 + (size_t)ct * KS2 * 128);
    const char* w3src = (const char*)(g_W3 + (size_t)ct * KS2 * 128);

    for (int t = 0; t < TQ; ++t) {
        int p = t & 1, q = p ^ 1;
        int use_gt = (t % cyc) < gn;
        const float* xsrc = use_gt ? (g_xfrag + (size_t)t * XFR) : (g_of + (size_t)q * XFR);

        // ---- layer 1: A = [x(256) | h1_prev(1024)] ----
        initacc(acc, g_bias1, ct, lane);
        layer_mm(acc, xsrc, KSX, g_h1 + (size_t)q * HFR, KS1, w1src, wsm, mb, ph, tid, w, lane);
        lstm_epi(acc, c1, g_h1 + (size_t)p * HFR, ct, w, lane);
        gen++; gridbar(gen);

        // ---- layer 2: A = [h1_cur | h2_prev] ----
        initacc(acc, g_bias2, ct, lane);
        layer_mm(acc, g_h1 + (size_t)p * HFR, KSH, g_h2 + (size_t)q * HFR, KS2, w2src,
                 wsm, mb, ph, tid, w, lane);
        lstm_epi(acc, c2, g_h2 + (size_t)p * HFR, ct, w, lane);
        gen++; gridbar(gen);

        // ---- layer 3: A = [h2_cur | h3_prev] ----
        initacc(acc, g_bias3, ct, lane);
        layer_mm(acc, g_h2 + (size_t)p * HFR, KSH, g_h3 + (size_t)q * HFR, KS2, w3src,
                 wsm, mb, ph, tid, w, lane);
        lstm_epi(acc, c3, g_h3 + (size_t)p * HFR, ct, w, lane);
        gen++; gridbar(gen);

        // ---- decoder (CTAs 0..21): out = h3 @ Wdec^T + b ----
        if (ct < DCTA) {
            float d0 = g_biasd[(ct << 3) + ((lane & 3) << 1)];
            float d1 = g_biasd[(ct << 3) + ((lane & 3) << 1) + 1];
            float dacc[4] = {d0, d1, d0, d1};
            const float2* wp = g_Wd + (size_t)ct * KSD * 32 + lane;
            const float4* A4 = (const float4*)(g_h3 + (size_t)p * HFR);
            float4 adb[8]; float2 wdb[8];
#pragma unroll
            for (int i = 0; i < 8; ++i) {
                adb[i] = __ldcg(A4 + (i * 8 + w) * 32 + lane);
                wdb[i] = wp[i * 32];
            }
#pragma unroll 8
            for (int ks = 0; ks < KSD; ++ks) {
                int s = ks & 7;
                float4 a = adb[s]; float2 b = wdb[s];
                int pf = ks + 8;
                if (pf < KSD) {
                    adb[s] = __ldcg(A4 + (pf * 8 + w) * 32 + lane);
                    wdb[s] = wp[pf * 32];
                }
                mma8(dacc, __float_as_uint(a.x), __float_as_uint(a.y), __float_as_uint(a.z),
                     __float_as_uint(a.w), __float_as_uint(b.x), __float_as_uint(b.y));
            }
            float* ofr = g_of + (size_t)p * XFR;
#pragma unroll
            for (int j = 0; j < 4; ++j) {
                int r = (lane >> 2) + ((j & 2) << 2);
                int c = ((lane & 3) << 1) + (j & 1);
                int b = (w << 4) + r;
                int oc = (ct << 3) + c;
                if (oc < OUTF) out[(b * TQ + t) * OUTF + oc] = dacc[j];
                int aq = ((c >= 4) ? 2 : 0) + ((r >= 8) ? 1 : 0);
                int lp = ((r & 7) << 2) + (c & 3);
                ofr[((((ct << 3) + w) << 5) + lp) * 4 + aq] = tf32r(dacc[j]);
            }
        }
        // 4th barrier only needed if next step reads decoder output (non-teacher-forced)
        int next_nontf = (t + 1 < TQ) && (((t + 1) % cyc) >= gn);
        if (next_nontf) { gen++; gridbar(gen); }
    }
}

// ----------------------------- launcher -----------------------------
extern "C" void kernel_launch(void* const* d_in, const int* in_sizes, int n_in,
                              void* d_out, int out_size) {
    const float* seq  = (const float*)d_in[0];
    const int*   pcn  = (const int*)d_in[1];
    const int*   pgn  = (const int*)d_in[2];
    const float* Wih1 = (const float*)d_in[3];
    const float* Whh1 = (const float*)d_in[4];
    const float* bih1 = (const float*)d_in[5];
    const float* bhh1 = (const float*)d_in[6];
    const float* Wih2 = (const float*)d_in[7];
    const float* Whh2 = (const float*)d_in[8];
    const float* bih2 = (const float*)d_in[9];
    const float* bhh2 = (const float*)d_in[10];
    const float* Wih3 = (const float*)d_in[11];
    const float* Whh3 = (const float*)d_in[12];
    const float* bih3 = (const float*)d_in[13];
    const float* bhh3 = (const float*)d_in[14];
    const float* Wdec = (const float*)d_in[15];
    const float* bdec = (const float*)d_in[16];

    // 2 setup launches, then lstm_main
    setup_all<<<(TQ * KSX * 256 + 255) / 256, 256>>>(bih1, bhh1, bih2, bhh2, bih3, bhh3,
                                                     bdec, Wdec, seq);
    {
        int total = NCTA * (KS1 + KS2 + KS2) * 128;
        fmt_layers<<<(total + 255) / 256, 256>>>(Wih1, Whh1, Wih2, Whh2, Wih3, Whh3);
    }
    lstm_main<<<NCTA, NTHR>>>(pcn, pgn, (float*)d_out);
}

// round 11
// speedup vs baseline: 2.2464x; 1.0207x over previous
#include <cuda_runtime.h>
#include <cstdint>

#define NCTA 128
#define NTHR 256
#define TQ   200
#define INF  171
#define OUTF 171
#define HIDQ 1024
#define KSX  32
#define KSH  128
#define KS1  (KSX + KSH)   // 160
#define KS2  (2 * KSH)     // 256
#define KSD  KSH
#define DCTA 22
#define HFR  (KSH * 1024)
#define XFR  (KSX * 1024)
#define CHKS 16
#define CHB  (CHKS * 1024)
#define NBUF 3
#define SMEMSZ (64 + NBUF * CHB)   // 64B mbarrier block + 3 x 16KB buffers

__device__ __align__(16) float2 g_W1[NCTA * KS1 * 128];
__device__ __align__(16) float2 g_W2[NCTA * KS2 * 128];
__device__ __align__(16) float2 g_W3[NCTA * KS2 * 128];
__device__ __align__(16) float2 g_Wd[DCTA * KSD * 32];
__device__ float g_bias1[4 * HIDQ];
__device__ float g_bias2[4 * HIDQ];
__device__ float g_bias3[4 * HIDQ];
__device__ float g_biasd[176];
__device__ __align__(16) float g_xfrag[TQ * XFR];
__device__ __align__(16) float g_h1[2 * HFR];
__device__ __align__(16) float g_h2[2 * HFR];
__device__ __align__(16) float g_h3[2 * HFR];
__device__ __align__(16) float g_of[2 * XFR];
__device__ unsigned g_cnt;           // monotonic, zero-init at load, never reset
__device__ volatile unsigned g_gen;

__device__ __forceinline__ float tf32r(float x) {
    uint32_t y;
    asm("cvt.rna.tf32.f32 %0, %1;" : "=r"(y) : "f"(x));
    return __uint_as_float(y);
}
__device__ __forceinline__ void mma8(float* c, uint32_t a0, uint32_t a1, uint32_t a2,
                                     uint32_t a3, uint32_t b0, uint32_t b1) {
    asm("mma.sync.aligned.m16n8k8.row.col.f32.tf32.tf32.f32 "
        "{%0,%1,%2,%3},{%4,%5,%6,%7},{%8,%9},{%0,%1,%2,%3};"
        : "+f"(c[0]), "+f"(c[1]), "+f"(c[2]), "+f"(c[3])
        : "r"(a0), "r"(a1), "r"(a2), "r"(a3), "r"(b0), "r"(b1));
}
__device__ __forceinline__ float sigm(float x) { return 1.f / (1.f + __expf(-x)); }
__device__ __forceinline__ uint32_t smem_u32(const void* p) {
    return (uint32_t)__cvta_generic_to_shared(p);
}
__device__ __forceinline__ void mbar_init(uint32_t a, uint32_t cnt) {
    asm volatile("mbarrier.init.shared.b64 [%0], %1;" :: "r"(a), "r"(cnt) : "memory");
}
__device__ __forceinline__ void mbar_expect_tx(uint32_t a, uint32_t bytes) {
    asm volatile("mbarrier.arrive.expect_tx.shared.b64 _, [%0], %1;"
                 :: "r"(a), "r"(bytes) : "memory");
}
__device__ __forceinline__ void bulk_g2s(uint32_t dst, const void* src, uint32_t bytes,
                                         uint32_t mbar) {
    asm volatile("cp.async.bulk.shared::cta.global.mbarrier::complete_tx::bytes "
                 "[%0], [%1], %2, [%3];"
                 :: "r"(dst), "l"(src), "r"(bytes), "r"(mbar) : "memory");
}
__device__ __forceinline__ void mbar_wait(uint32_t a, int parity) {
    asm volatile(
        "{\n\t.reg .pred P;\n\t"
        "WL%=:\n\t"
        "mbarrier.try_wait.parity.acquire.cta.shared::cta.b64 P, [%0], %1, 0x989680;\n\t"
        "@!P bra WL%=;\n\t}"
        :: "r"(a), "r"(parity) : "memory");
}
__device__ __forceinline__ float4 lds128(uint32_t a) {
    float4 v;
    asm volatile("ld.shared.v4.f32 {%0,%1,%2,%3}, [%4];"
                 : "=f"(v.x), "=f"(v.y), "=f"(v.z), "=f"(v.w) : "r"(a));
    return v;
}

// monotonic grid barrier: no reset, wrap-safe; all 128 CTAs resident (1/SM)
__device__ __forceinline__ void gridbar() {
    __syncthreads();
    if (threadIdx.x == 0) {
        __threadfence();
        unsigned arr = atomicAdd(&g_cnt, 1u);
        unsigned mygen = arr / NCTA + 1u;
        if (arr % NCTA == NCTA - 1u) {
            __threadfence();
            g_gen = mygen;
        } else {
            while ((int)(g_gen - mygen) < 0) { __nanosleep(32); }
        }
        __threadfence();
    }
    __syncthreads();
}

__device__ __forceinline__ void initacc(float acc[16], const float* bias, int ct, int lane) {
#pragma unroll
    for (int nt = 0; nt < 4; ++nt) {
        int col = nt * HIDQ + (ct << 3) + ((lane & 3) << 1);
        float b0 = bias[col], b1 = bias[col + 1];
        acc[4 * nt] = b0; acc[4 * nt + 1] = b1;
        acc[4 * nt + 2] = b0; acc[4 * nt + 3] = b1;
    }
}

// GEMM span: A via depth-8 __ldcg register ring; W via 3-deep TMA smem ring.
__device__ __forceinline__ void layer_mm(float acc[16], const float* A0, int nks0,
                                         const float* A1, int KS, const char* wsrc,
                                         const uint32_t* wsm, const uint32_t* mb,
                                         int* ph, int tid, int w, int lane) {
    const float4* A04 = (const float4*)A0;
    const float4* A14 = (const float4*)A1;
    float4 ab[8];
#pragma unroll
    for (int i = 0; i < 8; ++i)
        ab[i] = __ldcg(A04 + (i * 8 + w) * 32 + lane);

    int nch = KS >> 4;
    if (tid == 0) {
#pragma unroll
        for (int k = 0; k < 2; ++k) {
            mbar_expect_tx(mb[k], CHB);
            bulk_g2s(wsm[k], wsrc + (size_t)k * CHB, CHB, mb[k]);
        }
    }
    for (int c = 0; c < nch; ++c) {
        int b = c % NBUF;
        mbar_wait(mb[b], ph[b]);
        ph[b] ^= 1;
        uint32_t wbase = wsm[b] + (lane << 4);
#pragma unroll
        for (int j = 0; j < 16; ++j) {
            int ks = (c << 4) + j;
            int s = ks & 7;
            float4 a = ab[s];
            int pf = ks + 8;
            if (pf < KS) {
                const float4* src = (pf < nks0) ? (A04 + (pf * 8 + w) * 32)
                                                : (A14 + ((pf - nks0) * 8 + w) * 32);
                ab[s] = __ldcg(src + lane);
            }
            float4 w0 = lds128(wbase + j * 1024);
            float4 w1 = lds128(wbase + j * 1024 + 512);
            uint32_t a0 = __float_as_uint(a.x), a1 = __float_as_uint(a.y);
            uint32_t a2 = __float_as_uint(a.z), a3 = __float_as_uint(a.w);
            mma8(acc + 0,  a0, a1, a2, a3, __float_as_uint(w0.x), __float_as_uint(w0.y));
            mma8(acc + 4,  a0, a1, a2, a3, __float_as_uint(w0.z), __float_as_uint(w0.w));
            mma8(acc + 8,  a0, a1, a2, a3, __float_as_uint(w1.x), __float_as_uint(w1.y));
            mma8(acc + 12, a0, a1, a2, a3, __float_as_uint(w1.z), __float_as_uint(w1.w));
        }
        __syncthreads();
        if (tid == 0 && c + 2 < nch) {
            int b2 = (c + 2) % NBUF;
            mbar_expect_tx(mb[b2], CHB);
            bulk_g2s(wsm[b2], wsrc + (size_t)(c + 2) * CHB, CHB, mb[b2]);
        }
    }
}

__device__ __forceinline__ void lstm_epi(const float acc[16], float cst[4], float* hdst,
                                         int ct, int w, int lane) {
#pragma unroll
    for (int j = 0; j < 4; ++j) {
        float ig = sigm(acc[0 + j]);
        float fg = sigm(acc[4 + j]);
        float gg = tanhf(acc[8 + j]);
        float og = sigm(acc[12 + j]);
        float cc = fg * cst[j] + ig * gg;
        cst[j] = cc;
        float h = og * tanhf(cc);
        int r = (lane >> 2) + ((j & 2) << 2);
        int c = ((lane & 3) << 1) + (j & 1);
        int aq = ((c >= 4) ? 2 : 0) + ((r >= 8) ? 1 : 0);
        int lp = ((r & 7) << 2) + (c & 3);
        hdst[((((ct << 3) + w) << 5) + lp) * 4 + aq] = tf32r(h);
    }
}

__device__ __forceinline__ float wfetch(const float* Wih, const float* Whh, int gr, int k,
                                        int kxt, int kxv) {
    if (k < kxt) return (k < kxv) ? Wih[gr * kxv + k] : 0.f;
    return Whh[gr * HIDQ + (k - kxt)];
}
__device__ __forceinline__ void fmt_slice(float2* dst, const float* Wih, const float* Whh,
                                          int KS, int kxt, int kxv, int ct, int tid) {
    for (int i = tid; i < KS * 128; i += NTHR) {
        int nt = i & 3;
        int lane = (i >> 2) & 31;
        int ks = i >> 7;
        int gr = nt * HIDQ + (ct << 3) + (lane >> 2);
        int k0 = (ks << 3) + (lane & 3);
        float v0 = wfetch(Wih, Whh, gr, k0, kxt, kxv);
        float v1 = wfetch(Wih, Whh, gr, k0 + 4, kxt, kxv);
        size_t off = ((size_t)ct * KS + ks) * 128 + (nt >> 1) * 64 + lane * 2 + (nt & 1);
        dst[off] = make_float2(tf32r(v0), tf32r(v1));
    }
}
__device__ __forceinline__ float ldx(const float* s, int b, int t, int f) {
    return (f < INF) ? tf32r(s[(b * TQ + t) * INF + f]) : 0.f;
}

// ------------- single fused kernel: setup phase + persistent LSTM loop -------------
__global__ void __launch_bounds__(NTHR, 1)
lstm_main(const float* __restrict__ seq, const int* __restrict__ pcn,
          const int* __restrict__ pgn,
          const float* W_ih1, const float* W_hh1, const float* b_ih1, const float* b_hh1,
          const float* W_ih2, const float* W_hh2, const float* b_ih2, const float* b_hh2,
          const float* W_ih3, const float* W_hh3, const float* b_ih3, const float* b_hh3,
          const float* W_dec, const float* b_dec, float* __restrict__ out) {
    extern __shared__ __align__(16) char smem_dyn[];
    unsigned long long* s_mbar = (unsigned long long*)smem_dyn;   // first 64 B
    char* wbuf = smem_dyn + 64;                                   // NBUF x 16 KB

    int ct = blockIdx.x, tid = threadIdx.x, w = tid >> 5, lane = tid & 31;

    // ---------------- phase 0: formatting (weights local to this CTA) --------------
    fmt_slice(g_W1, W_ih1, W_hh1, KS1, 8 * KSX, INF, ct, tid);
    fmt_slice(g_W2, W_ih2, W_hh2, KS2, 1024, 1024, ct, tid);
    fmt_slice(g_W3, W_ih3, W_hh3, KS2, 1024, 1024, ct, tid);
    if (ct < DCTA) {
        for (int i = tid; i < KSD * 32; i += NTHR) {
            int ln = i & 31, ks = i >> 5;
            int orow = (ct << 3) + (ln >> 2);
            int k0 = (ks << 3) + (ln & 3);
            float v0 = (orow < OUTF) ? W_dec[orow * HIDQ + k0] : 0.f;
            float v1 = (orow < OUTF) ? W_dec[orow * HIDQ + k0 + 4] : 0.f;
            g_Wd[(size_t)ct * KSD * 32 + i] = make_float2(tf32r(v0), tf32r(v1));
        }
    }
    int gidx = ct * NTHR + tid;
    const int gstr = NCTA * NTHR;
    for (int i = gidx; i < TQ * KSX * 256; i += gstr) {
        int ln = i & 31, mt = (i >> 5) & 7, ks = (i >> 8) % KSX, t = i / (KSX * 256);
        int r = ln >> 2, cc = ln & 3;
        int b0 = (mt << 4) + r, f0 = (ks << 3) + cc;
        ((float4*)g_xfrag)[i] = make_float4(ldx(seq, b0, t, f0), ldx(seq, b0 + 8, t, f0),
                                            ldx(seq, b0, t, f0 + 4), ldx(seq, b0 + 8, t, f0 + 4));
    }
    for (int i = gidx; i < 2 * HFR; i += gstr) { g_h1[i] = 0.f; g_h2[i] = 0.f; g_h3[i] = 0.f; }
    for (int i = gidx; i < 2 * XFR; i += gstr) g_of[i] = 0.f;
    for (int i = gidx; i < 12288 + 176; i += gstr) {
        if (i < 4096) g_bias1[i] = b_ih1[i] + b_hh1[i];
        else if (i < 8192) { int k = i - 4096; g_bias2[k] = b_ih2[k] + b_hh2[k]; }
        else if (i < 12288) { int k = i - 8192; g_bias3[k] = b_ih3[k] + b_hh3[k]; }
        else { int oc = i - 12288; g_biasd[oc] = (oc < OUTF) ? b_dec[oc] : 0.f; }
    }

    uint32_t wsm[NBUF], mb[NBUF];
#pragma unroll
    for (int i = 0; i < NBUF; ++i) {
        wsm[i] = smem_u32(wbuf + (size_t)i * CHB);
        mb[i] = smem_u32(&s_mbar[i]);
    }
    if (tid == 0) {
#pragma unroll
        for (int i = 0; i < NBUF; ++i) mbar_init(mb[i], 1);
    }
    __threadfence();
    gridbar();                               // all formatting visible everywhere
    asm volatile("fence.proxy.async;" ::: "memory");  // order generic writes vs TMA reads

    // ---------------- phase 1: the 200-step recurrence ----------------
    int ph[NBUF] = {0, 0, 0};
    int cn = *pcn, gn = *pgn;
    int cyc = cn + gn;
    if (cyc <= 0) cyc = 1;
    float c1[4] = {0, 0, 0, 0}, c2[4] = {0, 0, 0, 0}, c3[4] = {0, 0, 0, 0};
    float acc[16];
    const char* w1src = (const char*)(g_W1 + (size_t)ct * KS1 * 128);
    const char* w2src = (const char*)(g_W2 + (size_t)ct * KS2 * 128);
    const char* w3src = (const char*)(g_W3 + (size_t)ct * KS2 * 128);

    for (int t = 0; t < TQ; ++t) {
        int p = t & 1, q = p ^ 1;
        int use_gt = (t % cyc) < gn;
        const float* xsrc = use_gt ? (g_xfrag + (size_t)t * XFR) : (g_of + (size_t)q * XFR);

        initacc(acc, g_bias1, ct, lane);
        layer_mm(acc, xsrc, KSX, g_h1 + (size_t)q * HFR, KS1, w1src, wsm, mb, ph, tid, w, lane);
        lstm_epi(acc, c1, g_h1 + (size_t)p * HFR, ct, w, lane);
        gridbar();

        initacc(acc, g_bias2, ct, lane);
        layer_mm(acc, g_h1 + (size_t)p * HFR, KSH, g_h2 + (size_t)q * HFR, KS2, w2src,
                 wsm, mb, ph, tid, w, lane);
        lstm_epi(acc, c2, g_h2 + (size_t)p * HFR, ct, w, lane);
        gridbar();

        initacc(acc, g_bias3, ct, lane);
        layer_mm(acc, g_h2 + (size_t)p * HFR, KSH, g_h3 + (size_t)q * HFR, KS2, w3src,
                 wsm, mb, ph, tid, w, lane);
        lstm_epi(acc, c3, g_h3 + (size_t)p * HFR, ct, w, lane);
        gridbar();

        if (ct < DCTA) {
            float d0 = g_biasd[(ct << 3) + ((lane & 3) << 1)];
            float d1 = g_biasd[(ct << 3) + ((lane & 3) << 1) + 1];
            float dacc[4] = {d0, d1, d0, d1};
            const float2* wp = g_Wd + (size_t)ct * KSD * 32 + lane;
            const float4* A4 = (const float4*)(g_h3 + (size_t)p * HFR);
            float4 adb[8]; float2 wdb[8];
#pragma unroll
            for (int i = 0; i < 8; ++i) {
                adb[i] = __ldcg(A4 + (i * 8 + w) * 32 + lane);
                wdb[i] = wp[i * 32];
            }
#pragma unroll 8
            for (int ks = 0; ks < KSD; ++ks) {
                int s = ks & 7;
                float4 a = adb[s]; float2 b = wdb[s];
                int pf = ks + 8;
                if (pf < KSD) {
                    adb[s] = __ldcg(A4 + (pf * 8 + w) * 32 + lane);
                    wdb[s] = wp[pf * 32];
                }
                mma8(dacc, __float_as_uint(a.x), __float_as_uint(a.y), __float_as_uint(a.z),
                     __float_as_uint(a.w), __float_as_uint(b.x), __float_as_uint(b.y));
            }
            float* ofr = g_of + (size_t)p * XFR;
#pragma unroll
            for (int j = 0; j < 4; ++j) {
                int r = (lane >> 2) + ((j & 2) << 2);
                int c = ((lane & 3) << 1) + (j & 1);
                int b = (w << 4) + r;
                int oc = (ct << 3) + c;
                if (oc < OUTF) out[(b * TQ + t) * OUTF + oc] = dacc[j];
                int aq = ((c >= 4) ? 2 : 0) + ((r >= 8) ? 1 : 0);
                int lp = ((r & 7) << 2) + (c & 3);
                ofr[((((ct << 3) + w) << 5) + lp) * 4 + aq] = tf32r(dacc[j]);
            }
        }
        int next_nontf = (t + 1 < TQ) && (((t + 1) % cyc) >= gn);
        if (next_nontf) gridbar();
    }
}

extern "C" void kernel_launch(void* const* d_in, const int* in_sizes, int n_in,
                              void* d_out, int out_size) {
    static int smem_set = 0;
    if (!smem_set) {
        cudaFuncSetAttribute(lstm_main, cudaFuncAttributeMaxDynamicSharedMemorySize, SMEMSZ);
        smem_set = 1;
    }
    lstm_main<<<NCTA, NTHR, SMEMSZ>>>(
        (const float*)d_in[0], (const int*)d_in[1], (const int*)d_in[2],
        (const float*)d_in[3], (const float*)d_in[4], (const float*)d_in[5],
        (const float*)d_in[6], (const float*)d_in[7], (const float*)d_in[8],
        (const float*)d_in[9], (const float*)d_in[10], (const float*)d_in[11],
        (const float*)d_in[12], (const float*)d_in[13], (const float*)d_in[14],
        (const float*)d_in[15], (const float*)d_in[16], (float*)d_out);
}

// round 12
// speedup vs baseline: 3.1141x; 1.3862x over previous
#include <cuda_runtime.h>
#include <cstdint>

#define NCTA 128
#define NTHR 512
#define TQ   200
#define INF  171
#define OUTF 171
#define HIDQ 1024
#define KSX  32
#define KSH  128
#define KS1  (KSX + KSH)   // 160
#define KS2  (2 * KSH)     // 256
#define KSD  128
#define DCTA 22
#define HFR  (KSH * 1024)
#define XFR  (KSX * 1024)
#define CHKS 16
#define CHB  (CHKS * 1024)
#define NBUF 3
#define REDOFF (64 + 6 * CHB)               // reduction buffer after 6 ring slots
#define SMEMSZ (REDOFF + 256 * 17 * 4)      // + 17-padded acc dump

__device__ __align__(16) float2 g_W1[NCTA * KS1 * 128];
__device__ __align__(16) float2 g_W2[NCTA * KS2 * 128];
__device__ __align__(16) float2 g_W3[NCTA * KS2 * 128];
__device__ __align__(16) float2 g_Wd[DCTA * KSD * 32];
__device__ float g_bias1[4 * HIDQ];
__device__ float g_bias2[4 * HIDQ];
__device__ float g_bias3[4 * HIDQ];
__device__ float g_biasd[176];
__device__ __align__(16) float g_xfrag[TQ * XFR];
__device__ __align__(16) float g_h1[2 * HFR];
__device__ __align__(16) float g_h2[2 * HFR];
__device__ __align__(16) float g_h3[2 * HFR];
__device__ __align__(16) float g_of[2 * XFR];
__device__ unsigned g_cnt;
__device__ volatile unsigned g_gen;

__device__ __forceinline__ float tf32r(float x) {
    uint32_t y;
    asm("cvt.rna.tf32.f32 %0, %1;" : "=r"(y) : "f"(x));
    return __uint_as_float(y);
}
__device__ __forceinline__ void mma8(float* c, uint32_t a0, uint32_t a1, uint32_t a2,
                                     uint32_t a3, uint32_t b0, uint32_t b1) {
    asm("mma.sync.aligned.m16n8k8.row.col.f32.tf32.tf32.f32 "
        "{%0,%1,%2,%3},{%4,%5,%6,%7},{%8,%9},{%0,%1,%2,%3};"
        : "+f"(c[0]), "+f"(c[1]), "+f"(c[2]), "+f"(c[3])
        : "r"(a0), "r"(a1), "r"(a2), "r"(a3), "r"(b0), "r"(b1));
}
__device__ __forceinline__ float sigm(float x) { return 1.f / (1.f + __expf(-x)); }
__device__ __forceinline__ uint32_t smem_u32(const void* p) {
    return (uint32_t)__cvta_generic_to_shared(p);
}
__device__ __forceinline__ void mbar_init(uint32_t a, uint32_t cnt) {
    asm volatile("mbarrier.init.shared.b64 [%0], %1;" :: "r"(a), "r"(cnt) : "memory");
}
__device__ __forceinline__ void mbar_expect_tx(uint32_t a, uint32_t bytes) {
    asm volatile("mbarrier.arrive.expect_tx.shared.b64 _, [%0], %1;"
                 :: "r"(a), "r"(bytes) : "memory");
}
__device__ __forceinline__ void bulk_g2s(uint32_t dst, const void* src, uint32_t bytes,
                                         uint32_t mbar) {
    asm volatile("cp.async.bulk.shared::cta.global.mbarrier::complete_tx::bytes "
                 "[%0], [%1], %2, [%3];"
                 :: "r"(dst), "l"(src), "r"(bytes), "r"(mbar) : "memory");
}
__device__ __forceinline__ void mbar_wait(uint32_t a, int parity) {
    asm volatile(
        "{\n\t.reg .pred P;\n\t"
        "WL%=:\n\t"
        "mbarrier.try_wait.parity.acquire.cta.shared::cta.b64 P, [%0], %1, 0x989680;\n\t"
        "@!P bra WL%=;\n\t}"
        :: "r"(a), "r"(parity) : "memory");
}
__device__ __forceinline__ float4 lds128(uint32_t a) {
    float4 v;
    asm volatile("ld.shared.v4.f32 {%0,%1,%2,%3}, [%4];"
                 : "=f"(v.x), "=f"(v.y), "=f"(v.z), "=f"(v.w) : "r"(a));
    return v;
}
__device__ __forceinline__ void barg(int g) {   // per-group named barrier (256 thr)
    asm volatile("bar.sync %0, %1;" :: "r"(g + 1), "r"(256) : "memory");
}

// monotonic grid barrier; all 128 CTAs resident (1/SM)
__device__ __forceinline__ void gridbar() {
    __syncthreads();
    if (threadIdx.x == 0) {
        __threadfence();
        unsigned arr = atomicAdd(&g_cnt, 1u);
        unsigned mygen = arr / NCTA + 1u;
        if (arr % NCTA == NCTA - 1u) {
            __threadfence();
            g_gen = mygen;
        } else {
            while ((int)(g_gen - mygen) < 0) { __nanosleep(32); }
        }
        __threadfence();
    }
    __syncthreads();
}

__device__ __forceinline__ void initacc(float acc[16], const float* bias, int ct, int lane) {
#pragma unroll
    for (int nt = 0; nt < 4; ++nt) {
        int col = nt * HIDQ + (ct << 3) + ((lane & 3) << 1);
        float b0 = bias[col], b1 = bias[col + 1];
        acc[4 * nt] = b0; acc[4 * nt + 1] = b1;
        acc[4 * nt + 2] = b0; acc[4 * nt + 3] = b1;
    }
}

// group-local GEMM span over ks [ksbase, ksbase+nksg): A via depth-8 __ldcg ring,
// W via this group's 3-deep TMA ring. nksg multiple of 16.
__device__ __forceinline__ void layer_mm(float acc[16], const float* A0, const float* A1,
                                         int nks0, int ksbase, int nksg, const char* wsrc,
                                         const uint32_t* wsm, const uint32_t* mb, int* ph,
                                         int g, int tid, int mt, int lane) {
    const float4* A04 = (const float4*)A0;
    const float4* A14 = (const float4*)A1;
    float4 ab[8];
#pragma unroll
    for (int i = 0; i < 8; ++i) {
        int ks = ksbase + i;
        const float4* src = (ks < nks0) ? (A04 + (ks * 8 + mt) * 32)
                                        : (A14 + ((ks - nks0) * 8 + mt) * 32);
        ab[i] = __ldcg(src + lane);
    }
    int nch = nksg >> 4;
    const char* wg = wsrc + (size_t)(ksbase >> 4) * CHB;
    if ((tid & 255) == 0) {
#pragma unroll
        for (int k = 0; k < 2; ++k) {
            mbar_expect_tx(mb[k], CHB);
            bulk_g2s(wsm[k], wg + (size_t)k * CHB, CHB, mb[k]);
        }
    }
    for (int c = 0; c < nch; ++c) {
        int b = c % NBUF;
        mbar_wait(mb[b], ph[b]);
        ph[b] ^= 1;
        uint32_t wb = wsm[b] + (lane << 4);
#pragma unroll
        for (int j = 0; j < 16; ++j) {
            int ksl = (c << 4) + j;
            int s = ksl & 7;
            float4 a = ab[s];
            int pf = ksl + 8;
            if (pf < nksg) {
                int ks = ksbase + pf;
                const float4* src = (ks < nks0) ? (A04 + (ks * 8 + mt) * 32)
                                                : (A14 + ((ks - nks0) * 8 + mt) * 32);
                ab[s] = __ldcg(src + lane);
            }
            float4 w0 = lds128(wb + j * 1024);
            float4 w1 = lds128(wb + j * 1024 + 512);
            uint32_t a0 = __float_as_uint(a.x), a1 = __float_as_uint(a.y);
            uint32_t a2 = __float_as_uint(a.z), a3 = __float_as_uint(a.w);
            mma8(acc + 0,  a0, a1, a2, a3, __float_as_uint(w0.x), __float_as_uint(w0.y));
            mma8(acc + 4,  a0, a1, a2, a3, __float_as_uint(w0.z), __float_as_uint(w0.w));
            mma8(acc + 8,  a0, a1, a2, a3, __float_as_uint(w1.x), __float_as_uint(w1.y));
            mma8(acc + 12, a0, a1, a2, a3, __float_as_uint(w1.z), __float_as_uint(w1.w));
        }
        barg(g);
        if ((tid & 255) == 0 && c + 2 < nch) {
            int b2 = (c + 2) % NBUF;
            mbar_expect_tx(mb[b2], CHB);
            bulk_g2s(wsm[b2], wg + (size_t)(c + 2) * CHB, CHB, mb[b2]);
        }
    }
}

__device__ __forceinline__ void lstm_epi(const float acc[16], float cst[4], float* hdst,
                                         int ct, int mt, int lane) {
#pragma unroll
    for (int j = 0; j < 4; ++j) {
        float ig = sigm(acc[0 + j]);
        float fg = sigm(acc[4 + j]);
        float gg = tanhf(acc[8 + j]);
        float og = sigm(acc[12 + j]);
        float cc = fg * cst[j] + ig * gg;
        cst[j] = cc;
        float h = og * tanhf(cc);
        int r = (lane >> 2) + ((j & 2) << 2);
        int c = ((lane & 3) << 1) + (j & 1);
        int aq = ((c >= 4) ? 2 : 0) + ((r >= 8) ? 1 : 0);
        int lp = ((r & 7) << 2) + (c & 3);
        hdst[((((ct << 3) + mt) << 5) + lp) * 4 + aq] = tf32r(h);
    }
}

__device__ __forceinline__ float wfetch(const float* Wih, const float* Whh, int gr, int k,
                                        int kxt, int kxv) {
    if (k < kxt) return (k < kxv) ? Wih[gr * kxv + k] : 0.f;
    return Whh[gr * HIDQ + (k - kxt)];
}
__device__ __forceinline__ void fmt_slice(float2* dst, const float* Wih, const float* Whh,
                                          int KS, int kxt, int kxv, int ct, int tid) {
    for (int i = tid; i < KS * 128; i += NTHR) {
        int nt = i & 3;
        int lane = (i >> 2) & 31;
        int ks = i >> 7;
        int gr = nt * HIDQ + (ct << 3) + (lane >> 2);
        int k0 = (ks << 3) + (lane & 3);
        float v0 = wfetch(Wih, Whh, gr, k0, kxt, kxv);
        float v1 = wfetch(Wih, Whh, gr, k0 + 4, kxt, kxv);
        size_t off = ((size_t)ct * KS + ks) * 128 + (nt >> 1) * 64 + lane * 2 + (nt & 1);
        dst[off] = make_float2(tf32r(v0), tf32r(v1));
    }
}
__device__ __forceinline__ float ldx(const float* s, int b, int t, int f) {
    return (f < INF) ? tf32r(s[(b * TQ + t) * INF + f]) : 0.f;
}

// ---------------- single fused kernel: setup + persistent LSTM ----------------
__global__ void __launch_bounds__(NTHR, 1)
lstm_main(const float* __restrict__ seq, const int* __restrict__ pcn,
          const int* __restrict__ pgn,
          const float* W_ih1, const float* W_hh1, const float* b_ih1, const float* b_hh1,
          const float* W_ih2, const float* W_hh2, const float* b_ih2, const float* b_hh2,
          const float* W_ih3, const float* W_hh3, const float* b_ih3, const float* b_hh3,
          const float* W_dec, const float* b_dec, float* __restrict__ out) {
    extern __shared__ __align__(16) char smem_dyn[];
    unsigned long long* s_mbar = (unsigned long long*)smem_dyn;   // 6 barriers in 64 B
    char* wbuf = smem_dyn + 64;                                   // 6 x 16 KB
    float* red = (float*)(smem_dyn + REDOFF);                     // 256 x 17 floats

    int ct = blockIdx.x, tid = threadIdx.x;
    int g = tid >> 8, w = tid >> 5, mt = w & 7, lane = tid & 31;

    // phase 0: formatting
    fmt_slice(g_W1, W_ih1, W_hh1, KS1, 8 * KSX, INF, ct, tid);
    fmt_slice(g_W2, W_ih2, W_hh2, KS2, 1024, 1024, ct, tid);
    fmt_slice(g_W3, W_ih3, W_hh3, KS2, 1024, 1024, ct, tid);
    if (ct < DCTA) {
        for (int i = tid; i < KSD * 32; i += NTHR) {
            int ln = i & 31, ks = i >> 5;
            int orow = (ct << 3) + (ln >> 2);
            int k0 = (ks << 3) + (ln & 3);
            float v0 = (orow < OUTF) ? W_dec[orow * HIDQ + k0] : 0.f;
            float v1 = (orow < OUTF) ? W_dec[orow * HIDQ + k0 + 4] : 0.f;
            g_Wd[(size_t)ct * KSD * 32 + i] = make_float2(tf32r(v0), tf32r(v1));
        }
    }
    int gidx = ct * NTHR + tid;
    const int gstr = NCTA * NTHR;
    for (int i = gidx; i < TQ * KSX * 256; i += gstr) {
        int ln = i & 31, m2 = (i >> 5) & 7, ks = (i >> 8) % KSX, t = i / (KSX * 256);
        int r = ln >> 2, cc = ln & 3;
        int b0 = (m2 << 4) + r, f0 = (ks << 3) + cc;
        ((float4*)g_xfrag)[i] = make_float4(ldx(seq, b0, t, f0), ldx(seq, b0 + 8, t, f0),
                                            ldx(seq, b0, t, f0 + 4), ldx(seq, b0 + 8, t, f0 + 4));
    }
    for (int i = gidx; i < 2 * HFR; i += gstr) { g_h1[i] = 0.f; g_h2[i] = 0.f; g_h3[i] = 0.f; }
    for (int i = gidx; i < 2 * XFR; i += gstr) g_of[i] = 0.f;
    for (int i = gidx; i < 12288 + 176; i += gstr) {
        if (i < 4096) g_bias1[i] = b_ih1[i] + b_hh1[i];
        else if (i < 8192) { int k = i - 4096; g_bias2[k] = b_ih2[k] + b_hh2[k]; }
        else if (i < 12288) { int k = i - 8192; g_bias3[k] = b_ih3[k] + b_hh3[k]; }
        else { int oc = i - 12288; g_biasd[oc] = (oc < OUTF) ? b_dec[oc] : 0.f; }
    }

    uint32_t wsm[NBUF], mb[NBUF];
#pragma unroll
    for (int i = 0; i < NBUF; ++i) {
        wsm[i] = smem_u32(wbuf + (size_t)(g * NBUF + i) * CHB);
        mb[i] = smem_u32(&s_mbar[g * NBUF + i]);
    }
    if (tid == 0) {
        for (int i = 0; i < 2 * NBUF; ++i) mbar_init(smem_u32(&s_mbar[i]), 1);
    }
    __threadfence();
    gridbar();
    asm volatile("fence.proxy.async;" ::: "memory");

    // phase 1: recurrence
    int ph[NBUF] = {0, 0, 0};
    int cn = *pcn, gn = *pgn;
    int cyc = cn + gn;
    if (cyc <= 0) cyc = 1;
    float c1[4] = {0, 0, 0, 0}, c2[4] = {0, 0, 0, 0}, c3[4] = {0, 0, 0, 0};
    float acc[16];
    const char* w1src = (const char*)(g_W1 + (size_t)ct * KS1 * 128);
    const char* w2src = (const char*)(g_W2 + (size_t)ct * KS2 * 128);
    const char* w3src = (const char*)(g_W3 + (size_t)ct * KS2 * 128);
    const int rb = (mt * 32 + lane) * 17;

    for (int t = 0; t < TQ; ++t) {
        int p = t & 1, q = p ^ 1;
        int use_gt = (t % cyc) < gn;
        const float* xsrc = use_gt ? (g_xfrag + (size_t)t * XFR) : (g_of + (size_t)q * XFR);

#pragma unroll 1
        for (int L = 0; L < 3; ++L) {
            const float* A0 = (L == 0) ? xsrc : ((L == 1) ? g_h1 + (size_t)p * HFR
                                                          : g_h2 + (size_t)p * HFR);
            const float* A1 = (L == 0) ? g_h1 + (size_t)q * HFR
                              : ((L == 1) ? g_h2 + (size_t)q * HFR : g_h3 + (size_t)q * HFR);
            int nks0 = (L == 0) ? KSX : KSH;
            int KS = (L == 0) ? KS1 : KS2;
            const char* wsrc = (L == 0) ? w1src : ((L == 1) ? w2src : w3src);
            const float* bias = (L == 0) ? g_bias1 : ((L == 1) ? g_bias2 : g_bias3);
            float* cst = (L == 0) ? c1 : ((L == 1) ? c2 : c3);
            float* hdst = (L == 0) ? g_h1 + (size_t)p * HFR
                          : ((L == 1) ? g_h2 + (size_t)p * HFR : g_h3 + (size_t)p * HFR);

            if (g == 0) initacc(acc, bias, ct, lane);
            else {
#pragma unroll
                for (int i = 0; i < 16; ++i) acc[i] = 0.f;
            }
            int half = KS >> 1;
            layer_mm(acc, A0, A1, nks0, g * half, half, wsrc, wsm, mb, ph, g, tid, mt, lane);
            __syncthreads();
            if (g == 1) {
#pragma unroll
                for (int i = 0; i < 16; ++i) red[rb + i] = acc[i];
            }
            __syncthreads();
            if (g == 0) {
#pragma unroll
                for (int i = 0; i < 16; ++i) acc[i] += red[rb + i];
                lstm_epi(acc, cst, hdst, ct, mt, lane);
            }
            gridbar();
        }

        // decoder (CTAs 0..21, group 0 warps)
        if (ct < DCTA && g == 0) {
            float d0 = g_biasd[(ct << 3) + ((lane & 3) << 1)];
            float d1 = g_biasd[(ct << 3) + ((lane & 3) << 1) + 1];
            float dacc[4] = {d0, d1, d0, d1};
            const float2* wp = g_Wd + (size_t)ct * KSD * 32 + lane;
            const float4* A4 = (const float4*)(g_h3 + (size_t)p * HFR);
            float4 adb[8]; float2 wdb[8];
#pragma unroll
            for (int i = 0; i < 8; ++i) {
                adb[i] = __ldcg(A4 + (i * 8 + mt) * 32 + lane);
                wdb[i] = wp[i * 32];
            }
#pragma unroll 8
            for (int ks = 0; ks < KSD; ++ks) {
                int s = ks & 7;
                float4 a = adb[s]; float2 b = wdb[s];
                int pf = ks + 8;
                if (pf < KSD) {
                    adb[s] = __ldcg(A4 + (pf * 8 + mt) * 32 + lane);
                    wdb[s] = wp[pf * 32];
                }
                mma8(dacc, __float_as_uint(a.x), __float_as_uint(a.y), __float_as_uint(a.z),
                     __float_as_uint(a.w), __float_as_uint(b.x), __float_as_uint(b.y));
            }
            float* ofr = g_of + (size_t)p * XFR;
#pragma unroll
            for (int j = 0; j < 4; ++j) {
                int r = (lane >> 2) + ((j & 2) << 2);
                int c = ((lane & 3) << 1) + (j & 1);
                int b = (mt << 4) + r;
                int oc = (ct << 3) + c;
                if (oc < OUTF) out[(b * TQ + t) * OUTF + oc] = dacc[j];
                int aq = ((c >= 4) ? 2 : 0) + ((r >= 8) ? 1 : 0);
                int lp = ((r & 7) << 2) + (c & 3);
                ofr[((((ct << 3) + mt) << 5) + lp) * 4 + aq] = tf32r(dacc[j]);
            }
        }
        int next_nontf = (t + 1 < TQ) && (((t + 1) % cyc) >= gn);
        if (next_nontf) gridbar();
    }
}

extern "C" void kernel_launch(void* const* d_in, const int* in_sizes, int n_in,
                              void* d_out, int out_size) {
    static int smem_set = 0;
    if (!smem_set) {
        cudaFuncSetAttribute(lstm_main, cudaFuncAttributeMaxDynamicSharedMemorySize, SMEMSZ);
        smem_set = 1;
    }
    lstm_main<<<NCTA, NTHR, SMEMSZ>>>(
        (const float*)d_in[0], (const int*)d_in[1], (const int*)d_in[2],
        (const float*)d_in[3], (const float*)d_in[4], (const float*)d_in[5],
        (const float*)d_in[6], (const float*)d_in[7], (const float*)d_in[8],
        (const float*)d_in[9], (const float*)d_in[10], (const float*)d_in[11],
        (const float*)d_in[12], (const float*)d_in[13], (const float*)d_in[14],
        (const float*)d_in[15], (const float*)d_in[16], (float*)d_out);
}